// round 13
// baseline (speedup 1.0000x reference)
#include <cuda_runtime.h>
#include <cuda_fp16.h>
#include <math_constants.h>
#include <mma.h>

using namespace nvcuda;

#define N_NODES 50000
#define NEDGE   1600000
#define HDIM    128
#define NUC     49232
#define NMC     512
#define NSC     256
#define NB      196      // scan blocks: 196*256 = 50176 >= N_NODES
#define LDH     136      // smem half-stride (mult of 8 for wmma fp16 ldm)
#define LDC     132      // smem float-stride for C (mult of 4)

// ---------------- scratch (device globals; no allocation allowed) ----------------
__device__ float  g_X[(size_t)N_NODES * HDIM];   // layer input / activated output
__device__ __half g_Hh[(size_t)N_NODES * HDIM];  // h = X @ W, fp16 for gather path
__device__ float  g_el[N_NODES];
__device__ float  g_er[N_NODES];
__device__ float  g_ebuf[NEDGE];                 // per-edge exp weights
__device__ int    g_deg[N_NODES];                // zero-initialized (.bss); re-zeroed by k_scan1
__device__ int    g_rowptr[N_NODES + 1];
__device__ int    g_pos[N_NODES];
__device__ int    g_esrc[NEDGE];                 // src ids sorted by dst
__device__ int    g_bsum[NB];
__device__ int    g_boff[NB];
__device__ float  g_T[NMC * HDIM];               // model @ Wb
__device__ __half g_Wh[4][HDIM * HDIM];          // hi halves of W1,W2,W3,Wb
__device__ __half g_Wl[4][HDIM * HDIM];          // lo halves

// ---------------- CSR build ----------------
// 4 edges per thread, int4 loads -> 4 overlapped atomics
__global__ void k_count(const int* __restrict__ dst) {
    int i = blockIdx.x * blockDim.x + threadIdx.x;
    if (i < NEDGE / 4) {
        int4 d = ((const int4*)dst)[i];
        atomicAdd(&g_deg[d.x], 1);
        atomicAdd(&g_deg[d.y], 1);
        atomicAdd(&g_deg[d.z], 1);
        atomicAdd(&g_deg[d.w], 1);
    }
}

// stage 1: per-block exclusive scan + block sums; also re-zeroes g_deg for the
// next graph replay (deterministic: g_deg starts zeroed from .bss / prior scan1)
__global__ void k_scan1() {
    __shared__ int wsum[8];
    __shared__ int wpre[8];
    int t = threadIdx.x, lane = t & 31, w = t >> 5;
    int idx = blockIdx.x * 256 + t;
    int v = (idx < N_NODES) ? g_deg[idx] : 0;
    if (idx < N_NODES) g_deg[idx] = 0;           // reset for next replay
    int incl = v;
    #pragma unroll
    for (int o = 1; o < 32; o <<= 1) {
        int y = __shfl_up_sync(0xffffffffu, incl, o);
        if (lane >= o) incl += y;
    }
    if (lane == 31) wsum[w] = incl;
    __syncthreads();
    if (t < 8) {
        int x = wsum[t], xs = x;
        #pragma unroll
        for (int o = 1; o < 8; o <<= 1) {
            int y = __shfl_up_sync(0xffu, xs, o);
            if (t >= o) xs += y;
        }
        wpre[t] = xs - x;
        if (t == 7) g_bsum[blockIdx.x] = xs;
    }
    __syncthreads();
    if (idx < N_NODES) g_rowptr[idx] = wpre[w] + incl - v;   // local exclusive
}

// stage 2: scan the 196 block sums
__global__ void k_scan2() {
    __shared__ int wsum[8];
    __shared__ int wpre[8];
    int t = threadIdx.x, lane = t & 31, w = t >> 5;
    int v = (t < NB) ? g_bsum[t] : 0;
    int incl = v;
    #pragma unroll
    for (int o = 1; o < 32; o <<= 1) {
        int y = __shfl_up_sync(0xffffffffu, incl, o);
        if (lane >= o) incl += y;
    }
    if (lane == 31) wsum[w] = incl;
    __syncthreads();
    if (t < 8) {
        int x = wsum[t], xs = x;
        #pragma unroll
        for (int o = 1; o < 8; o <<= 1) {
            int y = __shfl_up_sync(0xffu, xs, o);
            if (t >= o) xs += y;
        }
        wpre[t] = xs - x;
    }
    __syncthreads();
    if (t < NB) g_boff[t] = wpre[w] + incl - v;
    if (t == 0) g_rowptr[N_NODES] = NEDGE;
}

// stage 3: add block offsets
__global__ void k_scan3() {
    int t = threadIdx.x;
    int idx = blockIdx.x * 256 + t;
    if (idx < N_NODES) {
        int r = g_rowptr[idx] + g_boff[blockIdx.x];
        g_rowptr[idx] = r;
        g_pos[idx]    = r;
    }
}

// 4 edges per thread
__global__ void k_scatter(const int* __restrict__ src, const int* __restrict__ dst) {
    int i = blockIdx.x * blockDim.x + threadIdx.x;
    if (i < NEDGE / 4) {
        int4 s = ((const int4*)src)[i];
        int4 d = ((const int4*)dst)[i];
        int p0 = atomicAdd(&g_pos[d.x], 1);
        int p1 = atomicAdd(&g_pos[d.y], 1);
        int p2 = atomicAdd(&g_pos[d.z], 1);
        int p3 = atomicAdd(&g_pos[d.w], 1);
        g_esrc[p0] = s.x;
        g_esrc[p1] = s.y;
        g_esrc[p2] = s.z;
        g_esrc[p3] = s.w;
    }
}

// ---------------- split-fp16 helpers ----------------
__device__ __forceinline__ void split_h(float x, __half& h, __half& l) {
    h = __float2half_rn(x);
    l = __float2half_rn(x - __half2float(h));
}
__device__ __forceinline__ uint2 pack4(__half a, __half b, __half c, __half d) {
    __half2 p0 = __halves2half2(a, b);
    __half2 p1 = __halves2half2(c, d);
    uint2 u;
    u.x = *(unsigned*)&p0;
    u.y = *(unsigned*)&p1;
    return u;
}

// pre-split all four weight matrices into global hi/lo fp16 (runs once)
__global__ void k_splitw(const float* __restrict__ W1, const float* __restrict__ W2,
                         const float* __restrict__ W3, const float* __restrict__ Wb) {
    int i = blockIdx.x * blockDim.x + threadIdx.x;   // 0 .. 4*4096-1 (float4 units)
    int m = i >> 12;                                  // which matrix
    int j = i & 4095;                                 // float4 index within matrix
    const float* Wsrc = (m == 0) ? W1 : (m == 1) ? W2 : (m == 2) ? W3 : Wb;
    float4 v = ((const float4*)Wsrc)[j];
    __half h0, h1, h2, h3, l0, l1, l2, l3;
    split_h(v.x, h0, l0); split_h(v.y, h1, l1);
    split_h(v.z, h2, l2); split_h(v.w, h3, l3);
    ((uint2*)g_Wh[m])[j] = pack4(h0, h1, h2, h3);
    ((uint2*)g_Wl[m])[j] = pack4(l0, l1, l2, l3);
}

// ---------------- GEMM (split-fp16 tensor cores, fp32-class accuracy) ----------------
// H = X @ W via C = Xhi*Whi + Xhi*Wlo + Xlo*Whi (HMMA, fp32 accumulate).
// W halves pre-split in GLOBAL (L1-resident, 32 KB each): b-frags loaded straight
// from global, only the X tile lives in smem (34.8 KB -> ~6 CTAs/SM).
// 256 threads (8 warps), block tile 64 rows x 128 cols. warp w: row-tile w>>1,
// col half (w&1)*64. Accumulators -> smem C, then epilogue (fp16 Yh / fp32 Yf
// + fused el/er dots; warp owns 8 rows).
__global__ void k_gemm(const float* __restrict__ X,
                       const __half* __restrict__ wh, const __half* __restrict__ wl,
                       float* __restrict__ Yf, __half* __restrict__ Yh, int nrows,
                       const float* __restrict__ al, const float* __restrict__ ar) {
    extern __shared__ __align__(16) char smem_raw[];
    __half* xh = (__half*)smem_raw;        // 64 x LDH
    __half* xl = xh + 64 * LDH;            // 64 x LDH
    float*  Cs = (float*)smem_raw;         // 64 x LDC (reused after mainloop)
    int t = threadIdx.x;
    int row0 = blockIdx.x * 64;

    // stage X tile [64x128] as hi/lo fp16
    const float4* X4 = (const float4*)X;
    #pragma unroll 2
    for (int i = t; i < 2048; i += 256) {
        int r = i >> 5, c4 = (i & 31) * 4;
        float4 v = make_float4(0.f, 0.f, 0.f, 0.f);
        if (row0 + r < nrows) v = X4[(size_t)(row0 + r) * 32 + (i & 31)];
        __half h0, h1, h2, h3, l0, l1, l2, l3;
        split_h(v.x, h0, l0); split_h(v.y, h1, l1);
        split_h(v.z, h2, l2); split_h(v.w, h3, l3);
        *(uint2*)(xh + r * LDH + c4) = pack4(h0, h1, h2, h3);
        *(uint2*)(xl + r * LDH + c4) = pack4(l0, l1, l2, l3);
    }
    __syncthreads();

    int w  = t >> 5;
    int rt = w >> 1;                 // row-tile 0..3 (16 rows each)
    int c0 = (w & 1) * 64;           // col base 0 or 64

    wmma::fragment<wmma::accumulator, 16, 16, 16, float> acc[4];
    #pragma unroll
    for (int j = 0; j < 4; j++) wmma::fill_fragment(acc[j], 0.f);

    #pragma unroll
    for (int k = 0; k < 8; k++) {
        wmma::fragment<wmma::matrix_a, 16, 16, 16, __half, wmma::row_major> ah, alo;
        wmma::load_matrix_sync(ah,  xh + rt * 16 * LDH + k * 16, LDH);
        wmma::load_matrix_sync(alo, xl + rt * 16 * LDH + k * 16, LDH);
        #pragma unroll
        for (int j = 0; j < 4; j++) {
            wmma::fragment<wmma::matrix_b, 16, 16, 16, __half, wmma::row_major> bh, blo;
            wmma::load_matrix_sync(bh,  wh + k * 16 * HDIM + c0 + j * 16, HDIM);
            wmma::load_matrix_sync(blo, wl + k * 16 * HDIM + c0 + j * 16, HDIM);
            wmma::mma_sync(acc[j], ah,  bh,  acc[j]);
            wmma::mma_sync(acc[j], ah,  blo, acc[j]);
            wmma::mma_sync(acc[j], alo, bh,  acc[j]);
        }
    }
    __syncthreads();   // all warps done reading xh/xl before overwrite as C

    #pragma unroll
    for (int j = 0; j < 4; j++)
        wmma::store_matrix_sync(Cs + rt * 16 * LDC + c0 + j * 16, acc[j], LDC,
                                wmma::mem_row_major);
    __syncthreads();

    // epilogue: warp owns 8 rows (all 128 cols across 32 lanes x 4 cols)
    int lane = t & 31;
    int cj = lane * 4;
    int r0 = w * 8;
    float4 a4 = make_float4(0.f, 0.f, 0.f, 0.f), r4 = a4;
    if (al != nullptr) {
        a4 = ((const float4*)al)[lane];
        r4 = ((const float4*)ar)[lane];
    }
    #pragma unroll
    for (int r = 0; r < 8; r++) {
        int row = row0 + r0 + r;
        float4 v;
        v.x = Cs[(r0 + r) * LDC + cj + 0];
        v.y = Cs[(r0 + r) * LDC + cj + 1];
        v.z = Cs[(r0 + r) * LDC + cj + 2];
        v.w = Cs[(r0 + r) * LDC + cj + 3];
        if (row < nrows) {
            if (Yh) {
                __half2 p0 = __floats2half2_rn(v.x, v.y);
                __half2 p1 = __floats2half2_rn(v.z, v.w);
                unsigned u0 = *(unsigned*)&p0;
                unsigned u1 = *(unsigned*)&p1;
                ((uint2*)Yh)[(size_t)row * 32 + lane] = make_uint2(u0, u1);
            }
            if (Yf)
                *(float4*)(Yf + (size_t)row * 128 + cj) = v;
        }
        if (al != nullptr) {
            float pl = v.x * a4.x + v.y * a4.y + v.z * a4.z + v.w * a4.w;
            float pr = v.x * r4.x + v.y * r4.y + v.z * r4.z + v.w * r4.w;
            #pragma unroll
            for (int o = 16; o; o >>= 1) {
                pl += __shfl_xor_sync(0xffffffffu, pl, o);
                pr += __shfl_xor_sync(0xffffffffu, pr, o);
            }
            if (lane == 0 && row < nrows) { g_el[row] = pl; g_er[row] = pr; }
        }
    }
}

// ---------------- fused softmax-attention + aggregation, one warp per dst node ----------------
// 2-pass max-free softmax: scores bounded (|e| << 80) so exp(e) is fp32-safe and
// the normalized result is algebraically identical to the max-subtracted form.
__global__ void k_node(const float* __restrict__ bvec, int do_relu) {
    int gw = (blockIdx.x * blockDim.x + threadIdx.x) >> 5;
    int lane = threadIdx.x & 31;
    if (gw >= N_NODES) return;
    int start = g_rowptr[gw];
    int end   = g_rowptr[gw + 1];
    float eld = g_el[gw];

    // pass A: exp(score) + segment sum (one MUFU per lane-edge)
    float ssum = 0.f;
    for (int i = start + lane; i < end; i += 32) {
        int s = g_esrc[i];
        float e = eld + g_er[s];
        e = (e > 0.f) ? e : 0.2f * e;     // leaky_relu 0.2
        float p = __expf(e);
        g_ebuf[i] = p;
        ssum += p;
    }
    #pragma unroll
    for (int o = 16; o; o >>= 1) ssum += __shfl_xor_sync(0xffffffffu, ssum, o);
    float inv = 1.f / (ssum + 1e-10f);
    __syncwarp();   // make cross-lane g_ebuf writes visible

    // pass B: weighted fp16 gather; lane owns 4 contiguous cols; no MUFU here
    float4 acc = make_float4(0.f, 0.f, 0.f, 0.f);
    const uint2* H2 = (const uint2*)g_Hh;
    #pragma unroll 4
    for (int i = start; i < end; i++) {
        float a = g_ebuf[i] * inv;        // broadcast load, precomputed exp
        int s = g_esrc[i];                // broadcast load
        uint2 raw = H2[(size_t)s * 32 + lane];
        __half2 h0 = *(__half2*)&raw.x;
        __half2 h1 = *(__half2*)&raw.y;
        float2 f0 = __half22float2(h0);
        float2 f1 = __half22float2(h1);
        acc.x += a * f0.x; acc.y += a * f0.y;
        acc.z += a * f1.x; acc.w += a * f1.y;
    }

    float4 b4 = ((const float4*)bvec)[lane];
    float4 o4 = make_float4(acc.x + b4.x, acc.y + b4.y, acc.z + b4.z, acc.w + b4.w);
    if (do_relu) {
        o4.x = fmaxf(o4.x, 0.f); o4.y = fmaxf(o4.y, 0.f);
        o4.z = fmaxf(o4.z, 0.f); o4.w = fmaxf(o4.w, 0.f);
    }
    ((float4*)g_X)[(size_t)gw * 32 + lane] = o4;
}

// ---------------- bilinear head: scores[m][s] = dot(T[m], server[s]) + bb ----------------
__global__ void k_scores(const float* __restrict__ bb, float* __restrict__ out) {
    __shared__ __align__(16) float Tm[16][132];
    __shared__ __align__(16) float Ss[16][132];
    int tx = threadIdx.x;       // s within tile
    int ty = threadIdx.y;       // m within tile
    int m0 = blockIdx.x * 16, s0 = blockIdx.y * 16;
    int t = ty * 16 + tx;
    for (int i = t; i < 512; i += 256) {
        int r = i >> 5, c = i & 31;
        float4 v = ((const float4*)g_T)[(size_t)(m0 + r) * 32 + c];
        *(float4*)&Tm[r][c * 4] = v;
        float4 w = ((const float4*)g_X)[(size_t)(NUC + NMC + s0 + r) * 32 + c];
        *(float4*)&Ss[r][c * 4] = w;
    }
    __syncthreads();
    float4 acc = make_float4(0.f, 0.f, 0.f, 0.f);
    #pragma unroll 8
    for (int k = 0; k < 32; k++) {
        float4 a = *(const float4*)&Tm[ty][k * 4];
        float4 b = *(const float4*)&Ss[tx][k * 4];
        acc.x += a.x * b.x; acc.y += a.y * b.y;
        acc.z += a.z * b.z; acc.w += a.w * b.w;
    }
    out[(m0 + ty) * NSC + (s0 + tx)] = acc.x + acc.y + acc.z + acc.w + bb[0];
}

// ---------------- host ----------------
extern "C" void kernel_launch(void* const* d_in, const int* in_sizes, int n_in,
                              void* d_out, int out_size) {
    const float* x   = (const float*)d_in[0];
    const int*   ei  = (const int*)  d_in[1];
    const int*   src = ei;
    const int*   dst = ei + NEDGE;
    const float* W1  = (const float*)d_in[2];
    const float* al1 = (const float*)d_in[3];
    const float* ar1 = (const float*)d_in[4];
    const float* b1  = (const float*)d_in[5];
    const float* W2  = (const float*)d_in[6];
    const float* al2 = (const float*)d_in[7];
    const float* ar2 = (const float*)d_in[8];
    const float* b2  = (const float*)d_in[9];
    const float* W3  = (const float*)d_in[10];
    const float* al3 = (const float*)d_in[11];
    const float* ar3 = (const float*)d_in[12];
    const float* b3  = (const float*)d_in[13];
    const float* Wb  = (const float*)d_in[14];
    const float* bb  = (const float*)d_in[15];
    float* out = (float*)d_out;

    void *pX_, *pHh_, *pT_, *pWh_, *pWl_;
    cudaGetSymbolAddress(&pX_, g_X);
    cudaGetSymbolAddress(&pHh_, g_Hh);
    cudaGetSymbolAddress(&pT_, g_T);
    cudaGetSymbolAddress(&pWh_, g_Wh);
    cudaGetSymbolAddress(&pWl_, g_Wl);
    float*  pX = (float*)pX_;
    __half* pH = (__half*)pHh_;
    float*  pT = (float*)pT_;
    __half* pWh = (__half*)pWh_;
    __half* pWl = (__half*)pWl_;

    const int smem_bytes = 64 * LDC * 4;   // max(xh+xl 34816, Cs 33792) = 34816
    cudaFuncSetAttribute(k_gemm, cudaFuncAttributeMaxDynamicSharedMemorySize, 35840);

    int warpgrid = (N_NODES * 32 + 255) / 256;
    int gemmgrid = (N_NODES + 63) / 64;
    (void)smem_bytes;

    // CSR build + weight split; gemm layer-1 at launch index 3 for ncu sampling.
    k_count  <<<(NEDGE / 4 + 255) / 256, 256>>>(dst);                           // 0
    k_scan1  <<<NB, 256>>>();                                                   // 1
    k_splitw <<<64, 256>>>(W1, W2, W3, Wb);                                     // 2
    k_gemm<<<gemmgrid, 256, 35840>>>(x, pWh, pWl, nullptr, pH, N_NODES, al1, ar1); // 3 (profiled)
    k_scan2  <<<1, 256>>>();                                                    // 4
    k_scan3  <<<NB, 256>>>();                                                   // 5
    k_scatter<<<(NEDGE / 4 + 255) / 256, 256>>>(src, dst);                      // 6

    // layer 1 aggregation
    k_node<<<warpgrid, 256>>>(b1, 1);
    // layer 2
    k_gemm<<<gemmgrid, 256, 35840>>>(pX, pWh + 1 * HDIM * HDIM, pWl + 1 * HDIM * HDIM,
                                     nullptr, pH, N_NODES, al2, ar2);
    k_node<<<warpgrid, 256>>>(b2, 1);
    // layer 3 (no relu)
    k_gemm<<<gemmgrid, 256, 35840>>>(pX, pWh + 2 * HDIM * HDIM, pWl + 2 * HDIM * HDIM,
                                     nullptr, pH, N_NODES, al3, ar3);
    k_node<<<warpgrid, 256>>>(b3, 0);

    // bilinear head
    k_gemm<<<(NMC + 63) / 64, 256, 35840>>>(pX + (size_t)NUC * HDIM,
                                            pWh + 3 * HDIM * HDIM, pWl + 3 * HDIM * HDIM,
                                            pT, nullptr, NMC, nullptr, nullptr);
    k_scores<<<dim3(NMC / 16, NSC / 16), dim3(16, 16)>>>(bb, out);
}

// round 14
// speedup vs baseline: 1.4836x; 1.4836x over previous
#include <cuda_runtime.h>
#include <cuda_fp16.h>
#include <math_constants.h>
#include <mma.h>

using namespace nvcuda;

#define N_NODES 50000
#define NEDGE   1600000
#define HDIM    128
#define NUC     49232
#define NMC     512
#define NSC     256
#define NB      196      // scan blocks: 196*256 = 50176 >= N_NODES
#define LDH     136      // smem half-stride (mult of 8 for wmma fp16 ldm)
#define LDC     132      // smem float-stride for C (mult of 4)

// ---------------- scratch (device globals; no allocation allowed) ----------------
__device__ float  g_X[(size_t)N_NODES * HDIM];   // layer input / activated output
__device__ __half g_Hh[(size_t)N_NODES * HDIM];  // h = X @ W, fp16 for gather path
__device__ float  g_el[N_NODES];
__device__ float  g_er[N_NODES];
__device__ float  g_ebuf[NEDGE];                 // per-edge exp weights
__device__ int    g_deg[N_NODES];                // zero-initialized (.bss); re-zeroed by k_scan1
__device__ int    g_rowptr[N_NODES + 1];
__device__ int    g_pos[N_NODES];
__device__ int    g_esrc[NEDGE];                 // src ids sorted by dst
__device__ int    g_bsum[NB];
__device__ int    g_boff[NB];
__device__ float  g_T[NMC * HDIM];               // model @ Wb
__device__ __half g_Wh[4][HDIM * HDIM];          // hi halves of W1,W2,W3,Wb
__device__ __half g_Wl[4][HDIM * HDIM];          // lo halves

// ---------------- CSR build ----------------
// 4 edges per thread, int4 loads -> 4 overlapped atomics
__global__ void k_count(const int* __restrict__ dst) {
    int i = blockIdx.x * blockDim.x + threadIdx.x;
    if (i < NEDGE / 4) {
        int4 d = ((const int4*)dst)[i];
        atomicAdd(&g_deg[d.x], 1);
        atomicAdd(&g_deg[d.y], 1);
        atomicAdd(&g_deg[d.z], 1);
        atomicAdd(&g_deg[d.w], 1);
    }
}

// stage 1: per-block exclusive scan + block sums; also re-zeroes g_deg for the
// next graph replay (deterministic: g_deg starts zeroed from .bss / prior scan1)
__global__ void k_scan1() {
    __shared__ int wsum[8];
    __shared__ int wpre[8];
    int t = threadIdx.x, lane = t & 31, w = t >> 5;
    int idx = blockIdx.x * 256 + t;
    int v = (idx < N_NODES) ? g_deg[idx] : 0;
    if (idx < N_NODES) g_deg[idx] = 0;           // reset for next replay
    int incl = v;
    #pragma unroll
    for (int o = 1; o < 32; o <<= 1) {
        int y = __shfl_up_sync(0xffffffffu, incl, o);
        if (lane >= o) incl += y;
    }
    if (lane == 31) wsum[w] = incl;
    __syncthreads();
    if (t < 8) {
        int x = wsum[t], xs = x;
        #pragma unroll
        for (int o = 1; o < 8; o <<= 1) {
            int y = __shfl_up_sync(0xffu, xs, o);
            if (t >= o) xs += y;
        }
        wpre[t] = xs - x;
        if (t == 7) g_bsum[blockIdx.x] = xs;
    }
    __syncthreads();
    if (idx < N_NODES) g_rowptr[idx] = wpre[w] + incl - v;   // local exclusive
}

// stage 2: scan the 196 block sums
__global__ void k_scan2() {
    __shared__ int wsum[8];
    __shared__ int wpre[8];
    int t = threadIdx.x, lane = t & 31, w = t >> 5;
    int v = (t < NB) ? g_bsum[t] : 0;
    int incl = v;
    #pragma unroll
    for (int o = 1; o < 32; o <<= 1) {
        int y = __shfl_up_sync(0xffffffffu, incl, o);
        if (lane >= o) incl += y;
    }
    if (lane == 31) wsum[w] = incl;
    __syncthreads();
    if (t < 8) {
        int x = wsum[t], xs = x;
        #pragma unroll
        for (int o = 1; o < 8; o <<= 1) {
            int y = __shfl_up_sync(0xffu, xs, o);
            if (t >= o) xs += y;
        }
        wpre[t] = xs - x;
    }
    __syncthreads();
    if (t < NB) g_boff[t] = wpre[w] + incl - v;
    if (t == 0) g_rowptr[N_NODES] = NEDGE;
}

// stage 3: add block offsets
__global__ void k_scan3() {
    int t = threadIdx.x;
    int idx = blockIdx.x * 256 + t;
    if (idx < N_NODES) {
        int r = g_rowptr[idx] + g_boff[blockIdx.x];
        g_rowptr[idx] = r;
        g_pos[idx]    = r;
    }
}

// 4 edges per thread
__global__ void k_scatter(const int* __restrict__ src, const int* __restrict__ dst) {
    int i = blockIdx.x * blockDim.x + threadIdx.x;
    if (i < NEDGE / 4) {
        int4 s = ((const int4*)src)[i];
        int4 d = ((const int4*)dst)[i];
        int p0 = atomicAdd(&g_pos[d.x], 1);
        int p1 = atomicAdd(&g_pos[d.y], 1);
        int p2 = atomicAdd(&g_pos[d.z], 1);
        int p3 = atomicAdd(&g_pos[d.w], 1);
        g_esrc[p0] = s.x;
        g_esrc[p1] = s.y;
        g_esrc[p2] = s.z;
        g_esrc[p3] = s.w;
    }
}

// ---------------- split-fp16 helpers ----------------
__device__ __forceinline__ void split_h(float x, __half& h, __half& l) {
    h = __float2half_rn(x);
    l = __float2half_rn(x - __half2float(h));
}
__device__ __forceinline__ uint2 pack4(__half a, __half b, __half c, __half d) {
    __half2 p0 = __halves2half2(a, b);
    __half2 p1 = __halves2half2(c, d);
    uint2 u;
    u.x = *(unsigned*)&p0;
    u.y = *(unsigned*)&p1;
    return u;
}

// pre-split all four weight matrices into global hi/lo fp16 (runs once)
__global__ void k_splitw(const float* __restrict__ W1, const float* __restrict__ W2,
                         const float* __restrict__ W3, const float* __restrict__ Wb) {
    int i = blockIdx.x * blockDim.x + threadIdx.x;   // 0 .. 4*4096-1 (float4 units)
    int m = i >> 12;                                  // which matrix
    int j = i & 4095;                                 // float4 index within matrix
    const float* Wsrc = (m == 0) ? W1 : (m == 1) ? W2 : (m == 2) ? W3 : Wb;
    float4 v = ((const float4*)Wsrc)[j];
    __half h0, h1, h2, h3, l0, l1, l2, l3;
    split_h(v.x, h0, l0); split_h(v.y, h1, l1);
    split_h(v.z, h2, l2); split_h(v.w, h3, l3);
    ((uint2*)g_Wh[m])[j] = pack4(h0, h1, h2, h3);
    ((uint2*)g_Wl[m])[j] = pack4(l0, l1, l2, l3);
}

// ---------------- GEMM (split-fp16 tensor cores, fp32-class accuracy) ----------------
// H = X @ W via C = Xhi*Whi + Xhi*Wlo + Xlo*Whi (HMMA, fp32 accumulate).
// W halves pre-split once in global; each block COPIES them into smem with
// coalesced uint4 loads (no per-block conversion). X tile split in-block.
// 256 threads (8 warps), block tile 64 rows x 128 cols. warp w: row-tile w>>1,
// col half (w&1)*64. Accumulators -> smem C, then epilogue (fp16 Yh / fp32 Yf
// + fused el/er dots; warp owns 8 rows).
__global__ void k_gemm(const float* __restrict__ X,
                       const __half* __restrict__ wh, const __half* __restrict__ wl,
                       float* __restrict__ Yf, __half* __restrict__ Yh, int nrows,
                       const float* __restrict__ al, const float* __restrict__ ar) {
    extern __shared__ __align__(16) char smem_raw[];
    __half* xh  = (__half*)smem_raw;       // 64  x LDH
    __half* xl  = xh + 64 * LDH;           // 64  x LDH
    __half* whs = xl + 64 * LDH;           // 128 x LDH
    __half* wls = whs + 128 * LDH;         // 128 x LDH
    float*  Cs  = (float*)smem_raw;        // 64 x LDC (reused after mainloop)
    int t = threadIdx.x;
    int row0 = blockIdx.x * 64;

    // copy pre-split W halves [128x128 fp16 each] into smem (coalesced uint4)
    const uint4* Wh4 = (const uint4*)wh;   // 8 halves per uint4, 16 per row
    const uint4* Wl4 = (const uint4*)wl;
    #pragma unroll 4
    for (int i = t; i < 2048; i += 256) {
        int r = i >> 4, c8 = (i & 15) * 8;
        *(uint4*)(whs + r * LDH + c8) = Wh4[i];
        *(uint4*)(wls + r * LDH + c8) = Wl4[i];
    }
    // stage X tile [64x128] as hi/lo fp16
    const float4* X4 = (const float4*)X;
    #pragma unroll 2
    for (int i = t; i < 2048; i += 256) {
        int r = i >> 5, c4 = (i & 31) * 4;
        float4 v = make_float4(0.f, 0.f, 0.f, 0.f);
        if (row0 + r < nrows) v = X4[(size_t)(row0 + r) * 32 + (i & 31)];
        __half h0, h1, h2, h3, l0, l1, l2, l3;
        split_h(v.x, h0, l0); split_h(v.y, h1, l1);
        split_h(v.z, h2, l2); split_h(v.w, h3, l3);
        *(uint2*)(xh + r * LDH + c4) = pack4(h0, h1, h2, h3);
        *(uint2*)(xl + r * LDH + c4) = pack4(l0, l1, l2, l3);
    }
    __syncthreads();

    int w  = t >> 5;
    int rt = w >> 1;                 // row-tile 0..3 (16 rows each)
    int c0 = (w & 1) * 64;           // col base 0 or 64

    wmma::fragment<wmma::accumulator, 16, 16, 16, float> acc[4];
    #pragma unroll
    for (int j = 0; j < 4; j++) wmma::fill_fragment(acc[j], 0.f);

    #pragma unroll
    for (int k = 0; k < 8; k++) {
        wmma::fragment<wmma::matrix_a, 16, 16, 16, __half, wmma::row_major> ah, alo;
        wmma::load_matrix_sync(ah,  xh + rt * 16 * LDH + k * 16, LDH);
        wmma::load_matrix_sync(alo, xl + rt * 16 * LDH + k * 16, LDH);
        #pragma unroll
        for (int j = 0; j < 4; j++) {
            wmma::fragment<wmma::matrix_b, 16, 16, 16, __half, wmma::row_major> bh, blo;
            wmma::load_matrix_sync(bh,  whs + k * 16 * LDH + c0 + j * 16, LDH);
            wmma::load_matrix_sync(blo, wls + k * 16 * LDH + c0 + j * 16, LDH);
            wmma::mma_sync(acc[j], ah,  bh,  acc[j]);
            wmma::mma_sync(acc[j], ah,  blo, acc[j]);
            wmma::mma_sync(acc[j], alo, bh,  acc[j]);
        }
    }
    __syncthreads();   // all warps done reading xh/xl before overwrite as C

    #pragma unroll
    for (int j = 0; j < 4; j++)
        wmma::store_matrix_sync(Cs + rt * 16 * LDC + c0 + j * 16, acc[j], LDC,
                                wmma::mem_row_major);
    __syncthreads();

    // epilogue: warp owns 8 rows (all 128 cols across 32 lanes x 4 cols)
    int lane = t & 31;
    int cj = lane * 4;
    int r0 = w * 8;
    float4 a4 = make_float4(0.f, 0.f, 0.f, 0.f), r4 = a4;
    if (al != nullptr) {
        a4 = ((const float4*)al)[lane];
        r4 = ((const float4*)ar)[lane];
    }
    #pragma unroll
    for (int r = 0; r < 8; r++) {
        int row = row0 + r0 + r;
        float4 v;
        v.x = Cs[(r0 + r) * LDC + cj + 0];
        v.y = Cs[(r0 + r) * LDC + cj + 1];
        v.z = Cs[(r0 + r) * LDC + cj + 2];
        v.w = Cs[(r0 + r) * LDC + cj + 3];
        if (row < nrows) {
            if (Yh) {
                __half2 p0 = __floats2half2_rn(v.x, v.y);
                __half2 p1 = __floats2half2_rn(v.z, v.w);
                unsigned u0 = *(unsigned*)&p0;
                unsigned u1 = *(unsigned*)&p1;
                ((uint2*)Yh)[(size_t)row * 32 + lane] = make_uint2(u0, u1);
            }
            if (Yf)
                *(float4*)(Yf + (size_t)row * 128 + cj) = v;
        }
        if (al != nullptr) {
            float pl = v.x * a4.x + v.y * a4.y + v.z * a4.z + v.w * a4.w;
            float pr = v.x * r4.x + v.y * r4.y + v.z * r4.z + v.w * r4.w;
            #pragma unroll
            for (int o = 16; o; o >>= 1) {
                pl += __shfl_xor_sync(0xffffffffu, pl, o);
                pr += __shfl_xor_sync(0xffffffffu, pr, o);
            }
            if (lane == 0 && row < nrows) { g_el[row] = pl; g_er[row] = pr; }
        }
    }
}

// ---------------- fused softmax-attention + aggregation, one warp per dst node ----------------
// 2-pass max-free softmax: scores bounded (|e| << 80) so exp(e) is fp32-safe and
// the normalized result is algebraically identical to the max-subtracted form.
__global__ void k_node(const float* __restrict__ bvec, int do_relu) {
    int gw = (blockIdx.x * blockDim.x + threadIdx.x) >> 5;
    int lane = threadIdx.x & 31;
    if (gw >= N_NODES) return;
    int start = g_rowptr[gw];
    int end   = g_rowptr[gw + 1];
    float eld = g_el[gw];

    // pass A: exp(score) + segment sum (one MUFU per lane-edge)
    float ssum = 0.f;
    for (int i = start + lane; i < end; i += 32) {
        int s = g_esrc[i];
        float e = eld + g_er[s];
        e = (e > 0.f) ? e : 0.2f * e;     // leaky_relu 0.2
        float p = __expf(e);
        g_ebuf[i] = p;
        ssum += p;
    }
    #pragma unroll
    for (int o = 16; o; o >>= 1) ssum += __shfl_xor_sync(0xffffffffu, ssum, o);
    float inv = 1.f / (ssum + 1e-10f);
    __syncwarp();   // make cross-lane g_ebuf writes visible

    // pass B: weighted fp16 gather; lane owns 4 contiguous cols; no MUFU here
    float4 acc = make_float4(0.f, 0.f, 0.f, 0.f);
    const uint2* H2 = (const uint2*)g_Hh;
    #pragma unroll 4
    for (int i = start; i < end; i++) {
        float a = g_ebuf[i] * inv;        // broadcast load, precomputed exp
        int s = g_esrc[i];                // broadcast load
        uint2 raw = H2[(size_t)s * 32 + lane];
        __half2 h0 = *(__half2*)&raw.x;
        __half2 h1 = *(__half2*)&raw.y;
        float2 f0 = __half22float2(h0);
        float2 f1 = __half22float2(h1);
        acc.x += a * f0.x; acc.y += a * f0.y;
        acc.z += a * f1.x; acc.w += a * f1.y;
    }

    float4 b4 = ((const float4*)bvec)[lane];
    float4 o4 = make_float4(acc.x + b4.x, acc.y + b4.y, acc.z + b4.z, acc.w + b4.w);
    if (do_relu) {
        o4.x = fmaxf(o4.x, 0.f); o4.y = fmaxf(o4.y, 0.f);
        o4.z = fmaxf(o4.z, 0.f); o4.w = fmaxf(o4.w, 0.f);
    }
    ((float4*)g_X)[(size_t)gw * 32 + lane] = o4;
}

// ---------------- bilinear head: scores[m][s] = dot(T[m], server[s]) + bb ----------------
__global__ void k_scores(const float* __restrict__ bb, float* __restrict__ out) {
    __shared__ __align__(16) float Tm[16][132];
    __shared__ __align__(16) float Ss[16][132];
    int tx = threadIdx.x;       // s within tile
    int ty = threadIdx.y;       // m within tile
    int m0 = blockIdx.x * 16, s0 = blockIdx.y * 16;
    int t = ty * 16 + tx;
    for (int i = t; i < 512; i += 256) {
        int r = i >> 5, c = i & 31;
        float4 v = ((const float4*)g_T)[(size_t)(m0 + r) * 32 + c];
        *(float4*)&Tm[r][c * 4] = v;
        float4 w = ((const float4*)g_X)[(size_t)(NUC + NMC + s0 + r) * 32 + c];
        *(float4*)&Ss[r][c * 4] = w;
    }
    __syncthreads();
    float4 acc = make_float4(0.f, 0.f, 0.f, 0.f);
    #pragma unroll 8
    for (int k = 0; k < 32; k++) {
        float4 a = *(const float4*)&Tm[ty][k * 4];
        float4 b = *(const float4*)&Ss[tx][k * 4];
        acc.x += a.x * b.x; acc.y += a.y * b.y;
        acc.z += a.z * b.z; acc.w += a.w * b.w;
    }
    out[(m0 + ty) * NSC + (s0 + tx)] = acc.x + acc.y + acc.z + acc.w + bb[0];
}

// ---------------- host ----------------
extern "C" void kernel_launch(void* const* d_in, const int* in_sizes, int n_in,
                              void* d_out, int out_size) {
    const float* x   = (const float*)d_in[0];
    const int*   ei  = (const int*)  d_in[1];
    const int*   src = ei;
    const int*   dst = ei + NEDGE;
    const float* W1  = (const float*)d_in[2];
    const float* al1 = (const float*)d_in[3];
    const float* ar1 = (const float*)d_in[4];
    const float* b1  = (const float*)d_in[5];
    const float* W2  = (const float*)d_in[6];
    const float* al2 = (const float*)d_in[7];
    const float* ar2 = (const float*)d_in[8];
    const float* b2  = (const float*)d_in[9];
    const float* W3  = (const float*)d_in[10];
    const float* al3 = (const float*)d_in[11];
    const float* ar3 = (const float*)d_in[12];
    const float* b3  = (const float*)d_in[13];
    const float* Wb  = (const float*)d_in[14];
    const float* bb  = (const float*)d_in[15];
    float* out = (float*)d_out;

    void *pX_, *pHh_, *pT_, *pWh_, *pWl_;
    cudaGetSymbolAddress(&pX_, g_X);
    cudaGetSymbolAddress(&pHh_, g_Hh);
    cudaGetSymbolAddress(&pT_, g_T);
    cudaGetSymbolAddress(&pWh_, g_Wh);
    cudaGetSymbolAddress(&pWl_, g_Wl);
    float*  pX = (float*)pX_;
    __half* pH = (__half*)pHh_;
    float*  pT = (float*)pT_;
    __half* pWh = (__half*)pWh_;
    __half* pWl = (__half*)pWl_;

    const int smem_bytes = 384 * LDH * 2;   // xh+xl (64 each) + whs+wls (128 each) = 104448 B
    cudaFuncSetAttribute(k_gemm, cudaFuncAttributeMaxDynamicSharedMemorySize, smem_bytes);

    int warpgrid = (N_NODES * 32 + 255) / 256;
    int gemmgrid = (N_NODES + 63) / 64;

    // CSR build + weight split; gemm layer-1 at launch index 3 for ncu sampling.
    k_count  <<<(NEDGE / 4 + 255) / 256, 256>>>(dst);                           // 0
    k_scan1  <<<NB, 256>>>();                                                   // 1
    k_splitw <<<64, 256>>>(W1, W2, W3, Wb);                                     // 2
    k_gemm<<<gemmgrid, 256, smem_bytes>>>(x, pWh, pWl, nullptr, pH, N_NODES, al1, ar1); // 3 (profiled)
    k_scan2  <<<1, 256>>>();                                                    // 4
    k_scan3  <<<NB, 256>>>();                                                   // 5
    k_scatter<<<(NEDGE / 4 + 255) / 256, 256>>>(src, dst);                      // 6

    // layer 1 aggregation
    k_node<<<warpgrid, 256>>>(b1, 1);
    // layer 2
    k_gemm<<<gemmgrid, 256, smem_bytes>>>(pX, pWh + 1 * HDIM * HDIM, pWl + 1 * HDIM * HDIM,
                                          nullptr, pH, N_NODES, al2, ar2);
    k_node<<<warpgrid, 256>>>(b2, 1);
    // layer 3 (no relu)
    k_gemm<<<gemmgrid, 256, smem_bytes>>>(pX, pWh + 2 * HDIM * HDIM, pWl + 2 * HDIM * HDIM,
                                          nullptr, pH, N_NODES, al3, ar3);
    k_node<<<warpgrid, 256>>>(b3, 0);

    // bilinear head
    k_gemm<<<(NMC + 63) / 64, 256, smem_bytes>>>(pX + (size_t)NUC * HDIM,
                                                 pWh + 3 * HDIM * HDIM, pWl + 3 * HDIM * HDIM,
                                                 pT, nullptr, NMC, nullptr, nullptr);
    k_scores<<<dim3(NMC / 16, NSC / 16), dim3(16, 16)>>>(bb, out);
}

// round 15
// speedup vs baseline: 1.4931x; 1.0064x over previous
#include <cuda_runtime.h>
#include <cuda_fp16.h>
#include <math_constants.h>
#include <mma.h>

using namespace nvcuda;

#define N_NODES 50000
#define NEDGE   1600000
#define HDIM    128
#define NUC     49232
#define NMC     512
#define NSC     256
#define NB      196      // scan blocks: 196*256 = 50176 >= N_NODES
#define LDH     136      // smem half-stride (mult of 8 for wmma fp16 ldm)
#define LDC     132      // smem float-stride for C (mult of 4)

// ---------------- scratch (device globals; no allocation allowed) ----------------
__device__ float  g_X[(size_t)N_NODES * HDIM];   // layer input / activated output
__device__ __half g_Hh[(size_t)N_NODES * HDIM];  // h = X @ W, fp16 for gather path
__device__ float  g_el[N_NODES];
__device__ float  g_er[N_NODES];
__device__ float  g_ebuf[NEDGE];                 // per-edge exp weights
__device__ int    g_deg[N_NODES];                // zero-initialized (.bss); re-zeroed by k_scan1
__device__ int    g_rowptr[N_NODES + 1];
__device__ int    g_pos[N_NODES];
__device__ int    g_esrc[NEDGE];                 // src ids sorted by dst
__device__ int    g_bsum[NB];
__device__ int    g_boff[NB];
__device__ float  g_T[NMC * HDIM];               // model @ Wb
__device__ __half g_Wh[4][HDIM * HDIM];          // hi halves of W1,W2,W3,Wb
__device__ __half g_Wl[4][HDIM * HDIM];          // lo halves

// ---------------- CSR build ----------------
// 4 edges per thread, int4 loads -> 4 overlapped atomics
__global__ void k_count(const int* __restrict__ dst) {
    int i = blockIdx.x * blockDim.x + threadIdx.x;
    if (i < NEDGE / 4) {
        int4 d = ((const int4*)dst)[i];
        atomicAdd(&g_deg[d.x], 1);
        atomicAdd(&g_deg[d.y], 1);
        atomicAdd(&g_deg[d.z], 1);
        atomicAdd(&g_deg[d.w], 1);
    }
}

// stage 1: per-block exclusive scan + block sums; also re-zeroes g_deg for the
// next graph replay (deterministic: g_deg starts zeroed from .bss / prior scan1)
__global__ void k_scan1() {
    __shared__ int wsum[8];
    __shared__ int wpre[8];
    int t = threadIdx.x, lane = t & 31, w = t >> 5;
    int idx = blockIdx.x * 256 + t;
    int v = (idx < N_NODES) ? g_deg[idx] : 0;
    if (idx < N_NODES) g_deg[idx] = 0;           // reset for next replay
    int incl = v;
    #pragma unroll
    for (int o = 1; o < 32; o <<= 1) {
        int y = __shfl_up_sync(0xffffffffu, incl, o);
        if (lane >= o) incl += y;
    }
    if (lane == 31) wsum[w] = incl;
    __syncthreads();
    if (t < 8) {
        int x = wsum[t], xs = x;
        #pragma unroll
        for (int o = 1; o < 8; o <<= 1) {
            int y = __shfl_up_sync(0xffu, xs, o);
            if (t >= o) xs += y;
        }
        wpre[t] = xs - x;
        if (t == 7) g_bsum[blockIdx.x] = xs;
    }
    __syncthreads();
    if (idx < N_NODES) g_rowptr[idx] = wpre[w] + incl - v;   // local exclusive
}

// stage 2: scan the 196 block sums
__global__ void k_scan2() {
    __shared__ int wsum[8];
    __shared__ int wpre[8];
    int t = threadIdx.x, lane = t & 31, w = t >> 5;
    int v = (t < NB) ? g_bsum[t] : 0;
    int incl = v;
    #pragma unroll
    for (int o = 1; o < 32; o <<= 1) {
        int y = __shfl_up_sync(0xffffffffu, incl, o);
        if (lane >= o) incl += y;
    }
    if (lane == 31) wsum[w] = incl;
    __syncthreads();
    if (t < 8) {
        int x = wsum[t], xs = x;
        #pragma unroll
        for (int o = 1; o < 8; o <<= 1) {
            int y = __shfl_up_sync(0xffu, xs, o);
            if (t >= o) xs += y;
        }
        wpre[t] = xs - x;
    }
    __syncthreads();
    if (t < NB) g_boff[t] = wpre[w] + incl - v;
    if (t == 0) g_rowptr[N_NODES] = NEDGE;
}

// stage 3: add block offsets
__global__ void k_scan3() {
    int t = threadIdx.x;
    int idx = blockIdx.x * 256 + t;
    if (idx < N_NODES) {
        int r = g_rowptr[idx] + g_boff[blockIdx.x];
        g_rowptr[idx] = r;
        g_pos[idx]    = r;
    }
}

// 4 edges per thread
__global__ void k_scatter(const int* __restrict__ src, const int* __restrict__ dst) {
    int i = blockIdx.x * blockDim.x + threadIdx.x;
    if (i < NEDGE / 4) {
        int4 s = ((const int4*)src)[i];
        int4 d = ((const int4*)dst)[i];
        int p0 = atomicAdd(&g_pos[d.x], 1);
        int p1 = atomicAdd(&g_pos[d.y], 1);
        int p2 = atomicAdd(&g_pos[d.z], 1);
        int p3 = atomicAdd(&g_pos[d.w], 1);
        g_esrc[p0] = s.x;
        g_esrc[p1] = s.y;
        g_esrc[p2] = s.z;
        g_esrc[p3] = s.w;
    }
}

// ---------------- split-fp16 helpers ----------------
__device__ __forceinline__ void split_h(float x, __half& h, __half& l) {
    h = __float2half_rn(x);
    l = __float2half_rn(x - __half2float(h));
}
__device__ __forceinline__ uint2 pack4(__half a, __half b, __half c, __half d) {
    __half2 p0 = __halves2half2(a, b);
    __half2 p1 = __halves2half2(c, d);
    uint2 u;
    u.x = *(unsigned*)&p0;
    u.y = *(unsigned*)&p1;
    return u;
}

// pre-split all four weight matrices into global hi/lo fp16 (runs once)
__global__ void k_splitw(const float* __restrict__ W1, const float* __restrict__ W2,
                         const float* __restrict__ W3, const float* __restrict__ Wb) {
    int i = blockIdx.x * blockDim.x + threadIdx.x;   // 0 .. 4*4096-1 (float4 units)
    int m = i >> 12;                                  // which matrix
    int j = i & 4095;                                 // float4 index within matrix
    const float* Wsrc = (m == 0) ? W1 : (m == 1) ? W2 : (m == 2) ? W3 : Wb;
    float4 v = ((const float4*)Wsrc)[j];
    __half h0, h1, h2, h3, l0, l1, l2, l3;
    split_h(v.x, h0, l0); split_h(v.y, h1, l1);
    split_h(v.z, h2, l2); split_h(v.w, h3, l3);
    ((uint2*)g_Wh[m])[j] = pack4(h0, h1, h2, h3);
    ((uint2*)g_Wl[m])[j] = pack4(l0, l1, l2, l3);
}

// ---------------- GEMM (split-fp16 tensor cores, fp32-class accuracy) ----------------
// H = X @ W via C = Xhi*Whi + Xhi*Wlo + Xlo*Whi (HMMA, fp32 accumulate).
// Block tile 128 rows x 128 cols, 512 threads (16 warps) in a 4x4 warp grid:
// warp (wr,wc) computes rows wr*32..+31, cols wc*32..+31 (2x2 wmma tiles) --
// b-frags reused across 2 row-tiles, a-frags across 2 col-tiles (20% fewer LDSM
// vs 8-warp layout) and W staged once per 128 rows. Epilogue via smem C:
// fp16 Yh / fp32 Yf + fused el/er dots (each warp owns 8 full rows).
__global__ __launch_bounds__(512, 1)
void k_gemm(const float* __restrict__ X,
            const __half* __restrict__ wh, const __half* __restrict__ wl,
            float* __restrict__ Yf, __half* __restrict__ Yh, int nrows,
            const float* __restrict__ al, const float* __restrict__ ar) {
    extern __shared__ __align__(16) char smem_raw[];
    __half* xh  = (__half*)smem_raw;       // 128 x LDH
    __half* xl  = xh + 128 * LDH;          // 128 x LDH
    __half* whs = xl + 128 * LDH;          // 128 x LDH
    __half* wls = whs + 128 * LDH;         // 128 x LDH
    float*  Cs  = (float*)smem_raw;        // 128 x LDC (reused after mainloop)
    int t = threadIdx.x;
    int row0 = blockIdx.x * 128;

    // copy pre-split W halves [128x128 fp16 each] into smem (coalesced uint4)
    const uint4* Wh4 = (const uint4*)wh;   // 8 halves per uint4, 16 per row
    const uint4* Wl4 = (const uint4*)wl;
    #pragma unroll 4
    for (int i = t; i < 2048; i += 512) {
        int r = i >> 4, c8 = (i & 15) * 8;
        *(uint4*)(whs + r * LDH + c8) = Wh4[i];
        *(uint4*)(wls + r * LDH + c8) = Wl4[i];
    }
    // stage X tile [128x128] as hi/lo fp16
    const float4* X4 = (const float4*)X;
    #pragma unroll 2
    for (int i = t; i < 4096; i += 512) {
        int r = i >> 5, c4 = (i & 31) * 4;
        float4 v = make_float4(0.f, 0.f, 0.f, 0.f);
        if (row0 + r < nrows) v = X4[(size_t)(row0 + r) * 32 + (i & 31)];
        __half h0, h1, h2, h3, l0, l1, l2, l3;
        split_h(v.x, h0, l0); split_h(v.y, h1, l1);
        split_h(v.z, h2, l2); split_h(v.w, h3, l3);
        *(uint2*)(xh + r * LDH + c4) = pack4(h0, h1, h2, h3);
        *(uint2*)(xl + r * LDH + c4) = pack4(l0, l1, l2, l3);
    }
    __syncthreads();

    int w  = t >> 5;
    int wr = w >> 2;                 // warp row 0..3 (32 rows each)
    int wc = w & 3;                  // warp col 0..3 (32 cols each)

    wmma::fragment<wmma::accumulator, 16, 16, 16, float> acc[2][2];
    #pragma unroll
    for (int i = 0; i < 2; i++)
        #pragma unroll
        for (int j = 0; j < 2; j++) wmma::fill_fragment(acc[i][j], 0.f);

    #pragma unroll
    for (int k = 0; k < 8; k++) {
        wmma::fragment<wmma::matrix_a, 16, 16, 16, __half, wmma::row_major> ah[2], alo[2];
        #pragma unroll
        for (int i = 0; i < 2; i++) {
            wmma::load_matrix_sync(ah[i],  xh + (wr * 32 + i * 16) * LDH + k * 16, LDH);
            wmma::load_matrix_sync(alo[i], xl + (wr * 32 + i * 16) * LDH + k * 16, LDH);
        }
        #pragma unroll
        for (int j = 0; j < 2; j++) {
            wmma::fragment<wmma::matrix_b, 16, 16, 16, __half, wmma::row_major> bh, blo;
            wmma::load_matrix_sync(bh,  whs + k * 16 * LDH + wc * 32 + j * 16, LDH);
            wmma::load_matrix_sync(blo, wls + k * 16 * LDH + wc * 32 + j * 16, LDH);
            #pragma unroll
            for (int i = 0; i < 2; i++) {
                wmma::mma_sync(acc[i][j], ah[i],  bh,  acc[i][j]);
                wmma::mma_sync(acc[i][j], ah[i],  blo, acc[i][j]);
                wmma::mma_sync(acc[i][j], alo[i], bh,  acc[i][j]);
            }
        }
    }
    __syncthreads();   // all warps done reading xh/xl before overwrite as C

    #pragma unroll
    for (int i = 0; i < 2; i++)
        #pragma unroll
        for (int j = 0; j < 2; j++)
            wmma::store_matrix_sync(Cs + (wr * 32 + i * 16) * LDC + wc * 32 + j * 16,
                                    acc[i][j], LDC, wmma::mem_row_major);
    __syncthreads();

    // epilogue: warp owns 8 rows (all 128 cols across 32 lanes x 4 cols)
    int lane = t & 31;
    int cj = lane * 4;
    int r0 = w * 8;
    float4 a4 = make_float4(0.f, 0.f, 0.f, 0.f), r4 = a4;
    if (al != nullptr) {
        a4 = ((const float4*)al)[lane];
        r4 = ((const float4*)ar)[lane];
    }
    #pragma unroll
    for (int r = 0; r < 8; r++) {
        int row = row0 + r0 + r;
        float4 v;
        v.x = Cs[(r0 + r) * LDC + cj + 0];
        v.y = Cs[(r0 + r) * LDC + cj + 1];
        v.z = Cs[(r0 + r) * LDC + cj + 2];
        v.w = Cs[(r0 + r) * LDC + cj + 3];
        if (row < nrows) {
            if (Yh) {
                __half2 p0 = __floats2half2_rn(v.x, v.y);
                __half2 p1 = __floats2half2_rn(v.z, v.w);
                unsigned u0 = *(unsigned*)&p0;
                unsigned u1 = *(unsigned*)&p1;
                ((uint2*)Yh)[(size_t)row * 32 + lane] = make_uint2(u0, u1);
            }
            if (Yf)
                *(float4*)(Yf + (size_t)row * 128 + cj) = v;
        }
        if (al != nullptr) {
            float pl = v.x * a4.x + v.y * a4.y + v.z * a4.z + v.w * a4.w;
            float pr = v.x * r4.x + v.y * r4.y + v.z * r4.z + v.w * r4.w;
            #pragma unroll
            for (int o = 16; o; o >>= 1) {
                pl += __shfl_xor_sync(0xffffffffu, pl, o);
                pr += __shfl_xor_sync(0xffffffffu, pr, o);
            }
            if (lane == 0 && row < nrows) { g_el[row] = pl; g_er[row] = pr; }
        }
    }
}

// ---------------- fused softmax-attention + aggregation, one warp per dst node ----------------
// 2-pass max-free softmax: scores bounded (|e| << 80) so exp(e) is fp32-safe and
// the normalized result is algebraically identical to the max-subtracted form.
__global__ void k_node(const float* __restrict__ bvec, int do_relu) {
    int gw = (blockIdx.x * blockDim.x + threadIdx.x) >> 5;
    int lane = threadIdx.x & 31;
    if (gw >= N_NODES) return;
    int start = g_rowptr[gw];
    int end   = g_rowptr[gw + 1];
    float eld = g_el[gw];

    // pass A: exp(score) + segment sum (one MUFU per lane-edge)
    float ssum = 0.f;
    for (int i = start + lane; i < end; i += 32) {
        int s = g_esrc[i];
        float e = eld + g_er[s];
        e = (e > 0.f) ? e : 0.2f * e;     // leaky_relu 0.2
        float p = __expf(e);
        g_ebuf[i] = p;
        ssum += p;
    }
    #pragma unroll
    for (int o = 16; o; o >>= 1) ssum += __shfl_xor_sync(0xffffffffu, ssum, o);
    float inv = 1.f / (ssum + 1e-10f);
    __syncwarp();   // make cross-lane g_ebuf writes visible

    // pass B: weighted fp16 gather; lane owns 4 contiguous cols; no MUFU here
    float4 acc = make_float4(0.f, 0.f, 0.f, 0.f);
    const uint2* H2 = (const uint2*)g_Hh;
    #pragma unroll 4
    for (int i = start; i < end; i++) {
        float a = g_ebuf[i] * inv;        // broadcast load, precomputed exp
        int s = g_esrc[i];                // broadcast load
        uint2 raw = H2[(size_t)s * 32 + lane];
        __half2 h0 = *(__half2*)&raw.x;
        __half2 h1 = *(__half2*)&raw.y;
        float2 f0 = __half22float2(h0);
        float2 f1 = __half22float2(h1);
        acc.x += a * f0.x; acc.y += a * f0.y;
        acc.z += a * f1.x; acc.w += a * f1.y;
    }

    float4 b4 = ((const float4*)bvec)[lane];
    float4 o4 = make_float4(acc.x + b4.x, acc.y + b4.y, acc.z + b4.z, acc.w + b4.w);
    if (do_relu) {
        o4.x = fmaxf(o4.x, 0.f); o4.y = fmaxf(o4.y, 0.f);
        o4.z = fmaxf(o4.z, 0.f); o4.w = fmaxf(o4.w, 0.f);
    }
    ((float4*)g_X)[(size_t)gw * 32 + lane] = o4;
}

// ---------------- bilinear head: scores[m][s] = dot(T[m], server[s]) + bb ----------------
__global__ void k_scores(const float* __restrict__ bb, float* __restrict__ out) {
    __shared__ __align__(16) float Tm[16][132];
    __shared__ __align__(16) float Ss[16][132];
    int tx = threadIdx.x;       // s within tile
    int ty = threadIdx.y;       // m within tile
    int m0 = blockIdx.x * 16, s0 = blockIdx.y * 16;
    int t = ty * 16 + tx;
    for (int i = t; i < 512; i += 256) {
        int r = i >> 5, c = i & 31;
        float4 v = ((const float4*)g_T)[(size_t)(m0 + r) * 32 + c];
        *(float4*)&Tm[r][c * 4] = v;
        float4 w = ((const float4*)g_X)[(size_t)(NUC + NMC + s0 + r) * 32 + c];
        *(float4*)&Ss[r][c * 4] = w;
    }
    __syncthreads();
    float4 acc = make_float4(0.f, 0.f, 0.f, 0.f);
    #pragma unroll 8
    for (int k = 0; k < 32; k++) {
        float4 a = *(const float4*)&Tm[ty][k * 4];
        float4 b = *(const float4*)&Ss[tx][k * 4];
        acc.x += a.x * b.x; acc.y += a.y * b.y;
        acc.z += a.z * b.z; acc.w += a.w * b.w;
    }
    out[(m0 + ty) * NSC + (s0 + tx)] = acc.x + acc.y + acc.z + acc.w + bb[0];
}

// ---------------- host ----------------
extern "C" void kernel_launch(void* const* d_in, const int* in_sizes, int n_in,
                              void* d_out, int out_size) {
    const float* x   = (const float*)d_in[0];
    const int*   ei  = (const int*)  d_in[1];
    const int*   src = ei;
    const int*   dst = ei + NEDGE;
    const float* W1  = (const float*)d_in[2];
    const float* al1 = (const float*)d_in[3];
    const float* ar1 = (const float*)d_in[4];
    const float* b1  = (const float*)d_in[5];
    const float* W2  = (const float*)d_in[6];
    const float* al2 = (const float*)d_in[7];
    const float* ar2 = (const float*)d_in[8];
    const float* b2  = (const float*)d_in[9];
    const float* W3  = (const float*)d_in[10];
    const float* al3 = (const float*)d_in[11];
    const float* ar3 = (const float*)d_in[12];
    const float* b3  = (const float*)d_in[13];
    const float* Wb  = (const float*)d_in[14];
    const float* bb  = (const float*)d_in[15];
    float* out = (float*)d_out;

    void *pX_, *pHh_, *pT_, *pWh_, *pWl_;
    cudaGetSymbolAddress(&pX_, g_X);
    cudaGetSymbolAddress(&pHh_, g_Hh);
    cudaGetSymbolAddress(&pT_, g_T);
    cudaGetSymbolAddress(&pWh_, g_Wh);
    cudaGetSymbolAddress(&pWl_, g_Wl);
    float*  pX = (float*)pX_;
    __half* pH = (__half*)pHh_;
    float*  pT = (float*)pT_;
    __half* pWh = (__half*)pWh_;
    __half* pWl = (__half*)pWl_;

    const int smem_bytes = 4 * 128 * LDH * 2;   // xh+xl+whs+wls = 139264 B
    cudaFuncSetAttribute(k_gemm, cudaFuncAttributeMaxDynamicSharedMemorySize, smem_bytes);

    int warpgrid = (N_NODES * 32 + 255) / 256;
    int gemmgrid = (N_NODES + 127) / 128;

    // CSR build + weight split; gemm layer-1 at launch index 3 for ncu sampling.
    k_count  <<<(NEDGE / 4 + 255) / 256, 256>>>(dst);                           // 0
    k_scan1  <<<NB, 256>>>();                                                   // 1
    k_splitw <<<64, 256>>>(W1, W2, W3, Wb);                                     // 2
    k_gemm<<<gemmgrid, 512, smem_bytes>>>(x, pWh, pWl, nullptr, pH, N_NODES, al1, ar1); // 3 (profiled)
    k_scan2  <<<1, 256>>>();                                                    // 4
    k_scan3  <<<NB, 256>>>();                                                   // 5
    k_scatter<<<(NEDGE / 4 + 255) / 256, 256>>>(src, dst);                      // 6

    // layer 1 aggregation
    k_node<<<warpgrid, 256>>>(b1, 1);
    // layer 2
    k_gemm<<<gemmgrid, 512, smem_bytes>>>(pX, pWh + 1 * HDIM * HDIM, pWl + 1 * HDIM * HDIM,
                                          nullptr, pH, N_NODES, al2, ar2);
    k_node<<<warpgrid, 256>>>(b2, 1);
    // layer 3 (no relu)
    k_gemm<<<gemmgrid, 512, smem_bytes>>>(pX, pWh + 2 * HDIM * HDIM, pWl + 2 * HDIM * HDIM,
                                          nullptr, pH, N_NODES, al3, ar3);
    k_node<<<warpgrid, 256>>>(b3, 0);

    // bilinear head
    k_gemm<<<(NMC + 127) / 128, 512, smem_bytes>>>(pX + (size_t)NUC * HDIM,
                                                   pWh + 3 * HDIM * HDIM, pWl + 3 * HDIM * HDIM,
                                                   pT, nullptr, NMC, nullptr, nullptr);
    k_scores<<<dim3(NMC / 16, NSC / 16), dim3(16, 16)>>>(bb, out);
}

// round 16
// speedup vs baseline: 1.5354x; 1.0283x over previous
#include <cuda_runtime.h>
#include <cuda_fp16.h>
#include <math_constants.h>
#include <mma.h>

using namespace nvcuda;

#define N_NODES 50000
#define NEDGE   1600000
#define HDIM    128
#define NUC     49232
#define NMC     512
#define NSC     256
#define NB      196      // scan blocks: 196*256 = 50176 >= N_NODES
#define LDH     136      // smem half-stride (mult of 8 for wmma fp16 ldm)
#define LDC     132      // smem float-stride for C (mult of 4)

// ---------------- scratch (device globals; no allocation allowed) ----------------
__device__ float  g_X[(size_t)N_NODES * HDIM];   // layer input / activated output
__device__ __half g_Hh[(size_t)N_NODES * HDIM];  // h = X @ W, fp16 for gather path
__device__ float  g_el[N_NODES];
__device__ float  g_er[N_NODES];
__device__ float2 g_epk[NEDGE];                  // per-edge packed (exp weight, src bits)
__device__ int    g_deg[N_NODES];                // zero-initialized (.bss); re-zeroed by k_scan1
__device__ int    g_rowptr[N_NODES + 1];
__device__ int    g_pos[N_NODES];
__device__ int    g_esrc[NEDGE];                 // src ids sorted by dst
__device__ int    g_bsum[NB];
__device__ int    g_boff[NB];
__device__ float  g_T[NMC * HDIM];               // model @ Wb
__device__ __half g_Wh[4][HDIM * HDIM];          // hi halves of W1,W2,W3,Wb
__device__ __half g_Wl[4][HDIM * HDIM];          // lo halves

// ---------------- CSR build ----------------
// 4 edges per thread, int4 loads -> 4 overlapped atomics
__global__ void k_count(const int* __restrict__ dst) {
    int i = blockIdx.x * blockDim.x + threadIdx.x;
    if (i < NEDGE / 4) {
        int4 d = ((const int4*)dst)[i];
        atomicAdd(&g_deg[d.x], 1);
        atomicAdd(&g_deg[d.y], 1);
        atomicAdd(&g_deg[d.z], 1);
        atomicAdd(&g_deg[d.w], 1);
    }
}

// stage 1: per-block exclusive scan + block sums; also re-zeroes g_deg for the
// next graph replay (deterministic: g_deg starts zeroed from .bss / prior scan1)
__global__ void k_scan1() {
    __shared__ int wsum[8];
    __shared__ int wpre[8];
    int t = threadIdx.x, lane = t & 31, w = t >> 5;
    int idx = blockIdx.x * 256 + t;
    int v = (idx < N_NODES) ? g_deg[idx] : 0;
    if (idx < N_NODES) g_deg[idx] = 0;           // reset for next replay
    int incl = v;
    #pragma unroll
    for (int o = 1; o < 32; o <<= 1) {
        int y = __shfl_up_sync(0xffffffffu, incl, o);
        if (lane >= o) incl += y;
    }
    if (lane == 31) wsum[w] = incl;
    __syncthreads();
    if (t < 8) {
        int x = wsum[t], xs = x;
        #pragma unroll
        for (int o = 1; o < 8; o <<= 1) {
            int y = __shfl_up_sync(0xffu, xs, o);
            if (t >= o) xs += y;
        }
        wpre[t] = xs - x;
        if (t == 7) g_bsum[blockIdx.x] = xs;
    }
    __syncthreads();
    if (idx < N_NODES) g_rowptr[idx] = wpre[w] + incl - v;   // local exclusive
}

// stage 2: scan the 196 block sums
__global__ void k_scan2() {
    __shared__ int wsum[8];
    __shared__ int wpre[8];
    int t = threadIdx.x, lane = t & 31, w = t >> 5;
    int v = (t < NB) ? g_bsum[t] : 0;
    int incl = v;
    #pragma unroll
    for (int o = 1; o < 32; o <<= 1) {
        int y = __shfl_up_sync(0xffffffffu, incl, o);
        if (lane >= o) incl += y;
    }
    if (lane == 31) wsum[w] = incl;
    __syncthreads();
    if (t < 8) {
        int x = wsum[t], xs = x;
        #pragma unroll
        for (int o = 1; o < 8; o <<= 1) {
            int y = __shfl_up_sync(0xffu, xs, o);
            if (t >= o) xs += y;
        }
        wpre[t] = xs - x;
    }
    __syncthreads();
    if (t < NB) g_boff[t] = wpre[w] + incl - v;
    if (t == 0) g_rowptr[N_NODES] = NEDGE;
}

// stage 3: add block offsets
__global__ void k_scan3() {
    int t = threadIdx.x;
    int idx = blockIdx.x * 256 + t;
    if (idx < N_NODES) {
        int r = g_rowptr[idx] + g_boff[blockIdx.x];
        g_rowptr[idx] = r;
        g_pos[idx]    = r;
    }
}

// 4 edges per thread
__global__ void k_scatter(const int* __restrict__ src, const int* __restrict__ dst) {
    int i = blockIdx.x * blockDim.x + threadIdx.x;
    if (i < NEDGE / 4) {
        int4 s = ((const int4*)src)[i];
        int4 d = ((const int4*)dst)[i];
        int p0 = atomicAdd(&g_pos[d.x], 1);
        int p1 = atomicAdd(&g_pos[d.y], 1);
        int p2 = atomicAdd(&g_pos[d.z], 1);
        int p3 = atomicAdd(&g_pos[d.w], 1);
        g_esrc[p0] = s.x;
        g_esrc[p1] = s.y;
        g_esrc[p2] = s.z;
        g_esrc[p3] = s.w;
    }
}

// ---------------- split-fp16 helpers ----------------
__device__ __forceinline__ void split_h(float x, __half& h, __half& l) {
    h = __float2half_rn(x);
    l = __float2half_rn(x - __half2float(h));
}
__device__ __forceinline__ uint2 pack4(__half a, __half b, __half c, __half d) {
    __half2 p0 = __halves2half2(a, b);
    __half2 p1 = __halves2half2(c, d);
    uint2 u;
    u.x = *(unsigned*)&p0;
    u.y = *(unsigned*)&p1;
    return u;
}

// pre-split all four weight matrices into global hi/lo fp16 (runs once)
__global__ void k_splitw(const float* __restrict__ W1, const float* __restrict__ W2,
                         const float* __restrict__ W3, const float* __restrict__ Wb) {
    int i = blockIdx.x * blockDim.x + threadIdx.x;   // 0 .. 4*4096-1 (float4 units)
    int m = i >> 12;                                  // which matrix
    int j = i & 4095;                                 // float4 index within matrix
    const float* Wsrc = (m == 0) ? W1 : (m == 1) ? W2 : (m == 2) ? W3 : Wb;
    float4 v = ((const float4*)Wsrc)[j];
    __half h0, h1, h2, h3, l0, l1, l2, l3;
    split_h(v.x, h0, l0); split_h(v.y, h1, l1);
    split_h(v.z, h2, l2); split_h(v.w, h3, l3);
    ((uint2*)g_Wh[m])[j] = pack4(h0, h1, h2, h3);
    ((uint2*)g_Wl[m])[j] = pack4(l0, l1, l2, l3);
}

// ---------------- GEMM (split-fp16 tensor cores, fp32-class accuracy) ----------------
// H = X @ W via C = Xhi*Whi + Xhi*Wlo + Xlo*Whi (HMMA, fp32 accumulate).
// Block tile 128 rows x 128 cols, 512 threads (16 warps) in a 4x4 warp grid:
// warp (wr,wc) computes rows wr*32..+31, cols wc*32..+31 (2x2 wmma tiles).
// Epilogue via smem C: fp16 Yh / fp32 Yf + fused el/er dots (warp owns 8 rows).
__global__ __launch_bounds__(512, 1)
void k_gemm(const float* __restrict__ X,
            const __half* __restrict__ wh, const __half* __restrict__ wl,
            float* __restrict__ Yf, __half* __restrict__ Yh, int nrows,
            const float* __restrict__ al, const float* __restrict__ ar) {
    extern __shared__ __align__(16) char smem_raw[];
    __half* xh  = (__half*)smem_raw;       // 128 x LDH
    __half* xl  = xh + 128 * LDH;          // 128 x LDH
    __half* whs = xl + 128 * LDH;          // 128 x LDH
    __half* wls = whs + 128 * LDH;         // 128 x LDH
    float*  Cs  = (float*)smem_raw;        // 128 x LDC (reused after mainloop)
    int t = threadIdx.x;
    int row0 = blockIdx.x * 128;

    // copy pre-split W halves [128x128 fp16 each] into smem (coalesced uint4)
    const uint4* Wh4 = (const uint4*)wh;   // 8 halves per uint4, 16 per row
    const uint4* Wl4 = (const uint4*)wl;
    #pragma unroll 4
    for (int i = t; i < 2048; i += 512) {
        int r = i >> 4, c8 = (i & 15) * 8;
        *(uint4*)(whs + r * LDH + c8) = Wh4[i];
        *(uint4*)(wls + r * LDH + c8) = Wl4[i];
    }
    // stage X tile [128x128] as hi/lo fp16
    const float4* X4 = (const float4*)X;
    #pragma unroll 2
    for (int i = t; i < 4096; i += 512) {
        int r = i >> 5, c4 = (i & 31) * 4;
        float4 v = make_float4(0.f, 0.f, 0.f, 0.f);
        if (row0 + r < nrows) v = X4[(size_t)(row0 + r) * 32 + (i & 31)];
        __half h0, h1, h2, h3, l0, l1, l2, l3;
        split_h(v.x, h0, l0); split_h(v.y, h1, l1);
        split_h(v.z, h2, l2); split_h(v.w, h3, l3);
        *(uint2*)(xh + r * LDH + c4) = pack4(h0, h1, h2, h3);
        *(uint2*)(xl + r * LDH + c4) = pack4(l0, l1, l2, l3);
    }
    __syncthreads();

    int w  = t >> 5;
    int wr = w >> 2;                 // warp row 0..3 (32 rows each)
    int wc = w & 3;                  // warp col 0..3 (32 cols each)

    wmma::fragment<wmma::accumulator, 16, 16, 16, float> acc[2][2];
    #pragma unroll
    for (int i = 0; i < 2; i++)
        #pragma unroll
        for (int j = 0; j < 2; j++) wmma::fill_fragment(acc[i][j], 0.f);

    #pragma unroll
    for (int k = 0; k < 8; k++) {
        wmma::fragment<wmma::matrix_a, 16, 16, 16, __half, wmma::row_major> ah[2], alo[2];
        #pragma unroll
        for (int i = 0; i < 2; i++) {
            wmma::load_matrix_sync(ah[i],  xh + (wr * 32 + i * 16) * LDH + k * 16, LDH);
            wmma::load_matrix_sync(alo[i], xl + (wr * 32 + i * 16) * LDH + k * 16, LDH);
        }
        #pragma unroll
        for (int j = 0; j < 2; j++) {
            wmma::fragment<wmma::matrix_b, 16, 16, 16, __half, wmma::row_major> bh, blo;
            wmma::load_matrix_sync(bh,  whs + k * 16 * LDH + wc * 32 + j * 16, LDH);
            wmma::load_matrix_sync(blo, wls + k * 16 * LDH + wc * 32 + j * 16, LDH);
            #pragma unroll
            for (int i = 0; i < 2; i++) {
                wmma::mma_sync(acc[i][j], ah[i],  bh,  acc[i][j]);
                wmma::mma_sync(acc[i][j], ah[i],  blo, acc[i][j]);
                wmma::mma_sync(acc[i][j], alo[i], bh,  acc[i][j]);
            }
        }
    }
    __syncthreads();   // all warps done reading xh/xl before overwrite as C

    #pragma unroll
    for (int i = 0; i < 2; i++)
        #pragma unroll
        for (int j = 0; j < 2; j++)
            wmma::store_matrix_sync(Cs + (wr * 32 + i * 16) * LDC + wc * 32 + j * 16,
                                    acc[i][j], LDC, wmma::mem_row_major);
    __syncthreads();

    // epilogue: warp owns 8 rows (all 128 cols across 32 lanes x 4 cols)
    int lane = t & 31;
    int cj = lane * 4;
    int r0 = w * 8;
    float4 a4 = make_float4(0.f, 0.f, 0.f, 0.f), r4 = a4;
    if (al != nullptr) {
        a4 = ((const float4*)al)[lane];
        r4 = ((const float4*)ar)[lane];
    }
    #pragma unroll
    for (int r = 0; r < 8; r++) {
        int row = row0 + r0 + r;
        float4 v;
        v.x = Cs[(r0 + r) * LDC + cj + 0];
        v.y = Cs[(r0 + r) * LDC + cj + 1];
        v.z = Cs[(r0 + r) * LDC + cj + 2];
        v.w = Cs[(r0 + r) * LDC + cj + 3];
        if (row < nrows) {
            if (Yh) {
                __half2 p0 = __floats2half2_rn(v.x, v.y);
                __half2 p1 = __floats2half2_rn(v.z, v.w);
                unsigned u0 = *(unsigned*)&p0;
                unsigned u1 = *(unsigned*)&p1;
                ((uint2*)Yh)[(size_t)row * 32 + lane] = make_uint2(u0, u1);
            }
            if (Yf)
                *(float4*)(Yf + (size_t)row * 128 + cj) = v;
        }
        if (al != nullptr) {
            float pl = v.x * a4.x + v.y * a4.y + v.z * a4.z + v.w * a4.w;
            float pr = v.x * r4.x + v.y * r4.y + v.z * r4.z + v.w * r4.w;
            #pragma unroll
            for (int o = 16; o; o >>= 1) {
                pl += __shfl_xor_sync(0xffffffffu, pl, o);
                pr += __shfl_xor_sync(0xffffffffu, pr, o);
            }
            if (lane == 0 && row < nrows) { g_el[row] = pl; g_er[row] = pr; }
        }
    }
}

// ---------------- fused softmax-attention + aggregation, one warp per dst node ----------------
// 2-pass max-free softmax. pass A: p=exp(leaky(el+er)) packed WITH src id into
// g_epk (one 8B store). pass B: ONE 8B broadcast load per edge + fp16 row gather.
__global__ void k_node(const float* __restrict__ bvec, int do_relu) {
    int gw = (blockIdx.x * blockDim.x + threadIdx.x) >> 5;
    int lane = threadIdx.x & 31;
    if (gw >= N_NODES) return;
    int start = g_rowptr[gw];
    int end   = g_rowptr[gw + 1];
    float eld = g_el[gw];

    // pass A: exp(score) + segment sum; pack (weight, src) into one float2
    float ssum = 0.f;
    for (int i = start + lane; i < end; i += 32) {
        int s = g_esrc[i];
        float e = eld + g_er[s];
        e = (e > 0.f) ? e : 0.2f * e;     // leaky_relu 0.2
        float p = __expf(e);
        g_epk[i] = make_float2(p, __int_as_float(s));
        ssum += p;
    }
    #pragma unroll
    for (int o = 16; o; o >>= 1) ssum += __shfl_xor_sync(0xffffffffu, ssum, o);
    float inv = 1.f / (ssum + 1e-10f);
    __syncwarp();   // make cross-lane g_epk writes visible

    // pass B: single broadcast float2 load per edge + weighted fp16 gather
    float4 acc = make_float4(0.f, 0.f, 0.f, 0.f);
    const uint2* H2 = (const uint2*)g_Hh;
    #pragma unroll 4
    for (int i = start; i < end; i++) {
        float2 pk = g_epk[i];             // one 8B broadcast load
        float a = pk.x * inv;
        int s = __float_as_int(pk.y);
        uint2 raw = H2[(size_t)s * 32 + lane];
        __half2 h0 = *(__half2*)&raw.x;
        __half2 h1 = *(__half2*)&raw.y;
        float2 f0 = __half22float2(h0);
        float2 f1 = __half22float2(h1);
        acc.x += a * f0.x; acc.y += a * f0.y;
        acc.z += a * f1.x; acc.w += a * f1.y;
    }

    float4 b4 = ((const float4*)bvec)[lane];
    float4 o4 = make_float4(acc.x + b4.x, acc.y + b4.y, acc.z + b4.z, acc.w + b4.w);
    if (do_relu) {
        o4.x = fmaxf(o4.x, 0.f); o4.y = fmaxf(o4.y, 0.f);
        o4.z = fmaxf(o4.z, 0.f); o4.w = fmaxf(o4.w, 0.f);
    }
    ((float4*)g_X)[(size_t)gw * 32 + lane] = o4;
}

// ---------------- bilinear head: scores[m][s] = dot(T[m], server[s]) + bb ----------------
__global__ void k_scores(const float* __restrict__ bb, float* __restrict__ out) {
    __shared__ __align__(16) float Tm[16][132];
    __shared__ __align__(16) float Ss[16][132];
    int tx = threadIdx.x;       // s within tile
    int ty = threadIdx.y;       // m within tile
    int m0 = blockIdx.x * 16, s0 = blockIdx.y * 16;
    int t = ty * 16 + tx;
    for (int i = t; i < 512; i += 256) {
        int r = i >> 5, c = i & 31;
        float4 v = ((const float4*)g_T)[(size_t)(m0 + r) * 32 + c];
        *(float4*)&Tm[r][c * 4] = v;
        float4 w = ((const float4*)g_X)[(size_t)(NUC + NMC + s0 + r) * 32 + c];
        *(float4*)&Ss[r][c * 4] = w;
    }
    __syncthreads();
    float4 acc = make_float4(0.f, 0.f, 0.f, 0.f);
    #pragma unroll 8
    for (int k = 0; k < 32; k++) {
        float4 a = *(const float4*)&Tm[ty][k * 4];
        float4 b = *(const float4*)&Ss[tx][k * 4];
        acc.x += a.x * b.x; acc.y += a.y * b.y;
        acc.z += a.z * b.z; acc.w += a.w * b.w;
    }
    out[(m0 + ty) * NSC + (s0 + tx)] = acc.x + acc.y + acc.z + acc.w + bb[0];
}

// ---------------- host ----------------
extern "C" void kernel_launch(void* const* d_in, const int* in_sizes, int n_in,
                              void* d_out, int out_size) {
    const float* x   = (const float*)d_in[0];
    const int*   ei  = (const int*)  d_in[1];
    const int*   src = ei;
    const int*   dst = ei + NEDGE;
    const float* W1  = (const float*)d_in[2];
    const float* al1 = (const float*)d_in[3];
    const float* ar1 = (const float*)d_in[4];
    const float* b1  = (const float*)d_in[5];
    const float* W2  = (const float*)d_in[6];
    const float* al2 = (const float*)d_in[7];
    const float* ar2 = (const float*)d_in[8];
    const float* b2  = (const float*)d_in[9];
    const float* W3  = (const float*)d_in[10];
    const float* al3 = (const float*)d_in[11];
    const float* ar3 = (const float*)d_in[12];
    const float* b3  = (const float*)d_in[13];
    const float* Wb  = (const float*)d_in[14];
    const float* bb  = (const float*)d_in[15];
    float* out = (float*)d_out;

    void *pX_, *pHh_, *pT_, *pWh_, *pWl_;
    cudaGetSymbolAddress(&pX_, g_X);
    cudaGetSymbolAddress(&pHh_, g_Hh);
    cudaGetSymbolAddress(&pT_, g_T);
    cudaGetSymbolAddress(&pWh_, g_Wh);
    cudaGetSymbolAddress(&pWl_, g_Wl);
    float*  pX = (float*)pX_;
    __half* pH = (__half*)pHh_;
    float*  pT = (float*)pT_;
    __half* pWh = (__half*)pWh_;
    __half* pWl = (__half*)pWl_;

    const int smem_bytes = 4 * 128 * LDH * 2;   // xh+xl+whs+wls = 139264 B
    cudaFuncSetAttribute(k_gemm, cudaFuncAttributeMaxDynamicSharedMemorySize, smem_bytes);

    int warpgrid = (N_NODES * 32 + 255) / 256;
    int gemmgrid = (N_NODES + 127) / 128;

    // CSR build + weight split; gemm layer-1 at launch index 3 for ncu sampling.
    k_count  <<<(NEDGE / 4 + 255) / 256, 256>>>(dst);                           // 0
    k_scan1  <<<NB, 256>>>();                                                   // 1
    k_splitw <<<64, 256>>>(W1, W2, W3, Wb);                                     // 2
    k_gemm<<<gemmgrid, 512, smem_bytes>>>(x, pWh, pWl, nullptr, pH, N_NODES, al1, ar1); // 3 (profiled)
    k_scan2  <<<1, 256>>>();                                                    // 4
    k_scan3  <<<NB, 256>>>();                                                   // 5
    k_scatter<<<(NEDGE / 4 + 255) / 256, 256>>>(src, dst);                      // 6

    // layer 1 aggregation
    k_node<<<warpgrid, 256>>>(b1, 1);
    // layer 2
    k_gemm<<<gemmgrid, 512, smem_bytes>>>(pX, pWh + 1 * HDIM * HDIM, pWl + 1 * HDIM * HDIM,
                                          nullptr, pH, N_NODES, al2, ar2);
    k_node<<<warpgrid, 256>>>(b2, 1);
    // layer 3 (no relu)
    k_gemm<<<gemmgrid, 512, smem_bytes>>>(pX, pWh + 2 * HDIM * HDIM, pWl + 2 * HDIM * HDIM,
                                          nullptr, pH, N_NODES, al3, ar3);
    k_node<<<warpgrid, 256>>>(b3, 0);

    // bilinear head
    k_gemm<<<(NMC + 127) / 128, 512, smem_bytes>>>(pX + (size_t)NUC * HDIM,
                                                   pWh + 3 * HDIM * HDIM, pWl + 3 * HDIM * HDIM,
                                                   pT, nullptr, NMC, nullptr, nullptr);
    k_scores<<<dim3(NMC / 16, NSC / 16), dim3(16, 16)>>>(bb, out);
}

// round 17
// speedup vs baseline: 1.5601x; 1.0161x over previous
#include <cuda_runtime.h>
#include <cuda_fp16.h>
#include <math_constants.h>
#include <mma.h>

using namespace nvcuda;

#define N_NODES 50000
#define NEDGE   1600000
#define HDIM    128
#define NUC     49232
#define NMC     512
#define NSC     256
#define NB      196      // scan blocks: 196*256 = 50176 >= N_NODES
#define LDH     136      // smem half-stride (mult of 8 for wmma fp16 ldm)
#define LDC     132      // smem float-stride for C (mult of 4)

// ---------------- scratch (device globals; no allocation allowed) ----------------
__device__ float  g_X[(size_t)N_NODES * HDIM];   // layer input / activated output
__device__ __half g_Hh[(size_t)N_NODES * HDIM];  // h = X @ W, fp16 for gather path
__device__ float  g_el[N_NODES];
__device__ float  g_er[N_NODES];
__device__ float2 g_epk[NEDGE];                  // per-edge packed (exp weight, src bits)
__device__ int    g_deg[N_NODES];                // zero-initialized (.bss); re-zeroed by k_scan1
__device__ int    g_rowptr[N_NODES + 1];
__device__ int    g_pos[N_NODES];
__device__ int    g_esrc[NEDGE];                 // src ids sorted by dst
__device__ int    g_bsum[NB];
__device__ int    g_boff[NB];
__device__ float  g_T[NMC * HDIM];               // model @ Wb
__device__ __half g_Wh[4][HDIM * HDIM];          // hi halves of W1,W2,W3,Wb
__device__ __half g_Wl[4][HDIM * HDIM];          // lo halves

// ---------------- CSR build ----------------
// 4 edges per thread, int4 loads -> 4 overlapped atomics
__global__ void k_count(const int* __restrict__ dst) {
    int i = blockIdx.x * blockDim.x + threadIdx.x;
    if (i < NEDGE / 4) {
        int4 d = ((const int4*)dst)[i];
        atomicAdd(&g_deg[d.x], 1);
        atomicAdd(&g_deg[d.y], 1);
        atomicAdd(&g_deg[d.z], 1);
        atomicAdd(&g_deg[d.w], 1);
    }
}

// stage 1: per-block exclusive scan + block sums; also re-zeroes g_deg for the
// next graph replay (deterministic: g_deg starts zeroed from .bss / prior scan1)
__global__ void k_scan1() {
    __shared__ int wsum[8];
    __shared__ int wpre[8];
    int t = threadIdx.x, lane = t & 31, w = t >> 5;
    int idx = blockIdx.x * 256 + t;
    int v = (idx < N_NODES) ? g_deg[idx] : 0;
    if (idx < N_NODES) g_deg[idx] = 0;           // reset for next replay
    int incl = v;
    #pragma unroll
    for (int o = 1; o < 32; o <<= 1) {
        int y = __shfl_up_sync(0xffffffffu, incl, o);
        if (lane >= o) incl += y;
    }
    if (lane == 31) wsum[w] = incl;
    __syncthreads();
    if (t < 8) {
        int x = wsum[t], xs = x;
        #pragma unroll
        for (int o = 1; o < 8; o <<= 1) {
            int y = __shfl_up_sync(0xffu, xs, o);
            if (t >= o) xs += y;
        }
        wpre[t] = xs - x;
        if (t == 7) g_bsum[blockIdx.x] = xs;
    }
    __syncthreads();
    if (idx < N_NODES) g_rowptr[idx] = wpre[w] + incl - v;   // local exclusive
}

// stage 2: scan the 196 block sums
__global__ void k_scan2() {
    __shared__ int wsum[8];
    __shared__ int wpre[8];
    int t = threadIdx.x, lane = t & 31, w = t >> 5;
    int v = (t < NB) ? g_bsum[t] : 0;
    int incl = v;
    #pragma unroll
    for (int o = 1; o < 32; o <<= 1) {
        int y = __shfl_up_sync(0xffffffffu, incl, o);
        if (lane >= o) incl += y;
    }
    if (lane == 31) wsum[w] = incl;
    __syncthreads();
    if (t < 8) {
        int x = wsum[t], xs = x;
        #pragma unroll
        for (int o = 1; o < 8; o <<= 1) {
            int y = __shfl_up_sync(0xffu, xs, o);
            if (t >= o) xs += y;
        }
        wpre[t] = xs - x;
    }
    __syncthreads();
    if (t < NB) g_boff[t] = wpre[w] + incl - v;
    if (t == 0) g_rowptr[N_NODES] = NEDGE;
}

// stage 3: add block offsets
__global__ void k_scan3() {
    int t = threadIdx.x;
    int idx = blockIdx.x * 256 + t;
    if (idx < N_NODES) {
        int r = g_rowptr[idx] + g_boff[blockIdx.x];
        g_rowptr[idx] = r;
        g_pos[idx]    = r;
    }
}

// 4 edges per thread
__global__ void k_scatter(const int* __restrict__ src, const int* __restrict__ dst) {
    int i = blockIdx.x * blockDim.x + threadIdx.x;
    if (i < NEDGE / 4) {
        int4 s = ((const int4*)src)[i];
        int4 d = ((const int4*)dst)[i];
        int p0 = atomicAdd(&g_pos[d.x], 1);
        int p1 = atomicAdd(&g_pos[d.y], 1);
        int p2 = atomicAdd(&g_pos[d.z], 1);
        int p3 = atomicAdd(&g_pos[d.w], 1);
        g_esrc[p0] = s.x;
        g_esrc[p1] = s.y;
        g_esrc[p2] = s.z;
        g_esrc[p3] = s.w;
    }
}

// ---------------- split-fp16 helpers ----------------
__device__ __forceinline__ void split_h(float x, __half& h, __half& l) {
    h = __float2half_rn(x);
    l = __float2half_rn(x - __half2float(h));
}
__device__ __forceinline__ uint2 pack4(__half a, __half b, __half c, __half d) {
    __half2 p0 = __halves2half2(a, b);
    __half2 p1 = __halves2half2(c, d);
    uint2 u;
    u.x = *(unsigned*)&p0;
    u.y = *(unsigned*)&p1;
    return u;
}

// pre-split all four weight matrices into global hi/lo fp16 (runs once)
__global__ void k_splitw(const float* __restrict__ W1, const float* __restrict__ W2,
                         const float* __restrict__ W3, const float* __restrict__ Wb) {
    int i = blockIdx.x * blockDim.x + threadIdx.x;   // 0 .. 4*4096-1 (float4 units)
    int m = i >> 12;                                  // which matrix
    int j = i & 4095;                                 // float4 index within matrix
    const float* Wsrc = (m == 0) ? W1 : (m == 1) ? W2 : (m == 2) ? W3 : Wb;
    float4 v = ((const float4*)Wsrc)[j];
    __half h0, h1, h2, h3, l0, l1, l2, l3;
    split_h(v.x, h0, l0); split_h(v.y, h1, l1);
    split_h(v.z, h2, l2); split_h(v.w, h3, l3);
    ((uint2*)g_Wh[m])[j] = pack4(h0, h1, h2, h3);
    ((uint2*)g_Wl[m])[j] = pack4(l0, l1, l2, l3);
}

// ---------------- GEMM (split-fp16 tensor cores, fp32-class accuracy) ----------------
// H = X @ W via C = Xhi*Whi + Xhi*Wlo + Xlo*Whi (HMMA, fp32 accumulate).
// Block tile 128 rows x 128 cols, 512 threads (16 warps) in a 4x4 warp grid:
// warp (wr,wc) computes rows wr*32..+31, cols wc*32..+31 (2x2 wmma tiles).
// Epilogue via smem C: fp16 Yh / fp32 Yf + fused el/er dots (warp owns 8 rows).
__global__ __launch_bounds__(512, 1)
void k_gemm(const float* __restrict__ X,
            const __half* __restrict__ wh, const __half* __restrict__ wl,
            float* __restrict__ Yf, __half* __restrict__ Yh, int nrows,
            const float* __restrict__ al, const float* __restrict__ ar) {
    extern __shared__ __align__(16) char smem_raw[];
    __half* xh  = (__half*)smem_raw;       // 128 x LDH
    __half* xl  = xh + 128 * LDH;          // 128 x LDH
    __half* whs = xl + 128 * LDH;          // 128 x LDH
    __half* wls = whs + 128 * LDH;         // 128 x LDH
    float*  Cs  = (float*)smem_raw;        // 128 x LDC (reused after mainloop)
    int t = threadIdx.x;
    int row0 = blockIdx.x * 128;

    // copy pre-split W halves [128x128 fp16 each] into smem (coalesced uint4)
    const uint4* Wh4 = (const uint4*)wh;   // 8 halves per uint4, 16 per row
    const uint4* Wl4 = (const uint4*)wl;
    #pragma unroll 4
    for (int i = t; i < 2048; i += 512) {
        int r = i >> 4, c8 = (i & 15) * 8;
        *(uint4*)(whs + r * LDH + c8) = Wh4[i];
        *(uint4*)(wls + r * LDH + c8) = Wl4[i];
    }
    // stage X tile [128x128] as hi/lo fp16
    const float4* X4 = (const float4*)X;
    #pragma unroll 2
    for (int i = t; i < 4096; i += 512) {
        int r = i >> 5, c4 = (i & 31) * 4;
        float4 v = make_float4(0.f, 0.f, 0.f, 0.f);
        if (row0 + r < nrows) v = X4[(size_t)(row0 + r) * 32 + (i & 31)];
        __half h0, h1, h2, h3, l0, l1, l2, l3;
        split_h(v.x, h0, l0); split_h(v.y, h1, l1);
        split_h(v.z, h2, l2); split_h(v.w, h3, l3);
        *(uint2*)(xh + r * LDH + c4) = pack4(h0, h1, h2, h3);
        *(uint2*)(xl + r * LDH + c4) = pack4(l0, l1, l2, l3);
    }
    __syncthreads();

    int w  = t >> 5;
    int wr = w >> 2;                 // warp row 0..3 (32 rows each)
    int wc = w & 3;                  // warp col 0..3 (32 cols each)

    wmma::fragment<wmma::accumulator, 16, 16, 16, float> acc[2][2];
    #pragma unroll
    for (int i = 0; i < 2; i++)
        #pragma unroll
        for (int j = 0; j < 2; j++) wmma::fill_fragment(acc[i][j], 0.f);

    #pragma unroll
    for (int k = 0; k < 8; k++) {
        wmma::fragment<wmma::matrix_a, 16, 16, 16, __half, wmma::row_major> ah[2], alo[2];
        #pragma unroll
        for (int i = 0; i < 2; i++) {
            wmma::load_matrix_sync(ah[i],  xh + (wr * 32 + i * 16) * LDH + k * 16, LDH);
            wmma::load_matrix_sync(alo[i], xl + (wr * 32 + i * 16) * LDH + k * 16, LDH);
        }
        #pragma unroll
        for (int j = 0; j < 2; j++) {
            wmma::fragment<wmma::matrix_b, 16, 16, 16, __half, wmma::row_major> bh, blo;
            wmma::load_matrix_sync(bh,  whs + k * 16 * LDH + wc * 32 + j * 16, LDH);
            wmma::load_matrix_sync(blo, wls + k * 16 * LDH + wc * 32 + j * 16, LDH);
            #pragma unroll
            for (int i = 0; i < 2; i++) {
                wmma::mma_sync(acc[i][j], ah[i],  bh,  acc[i][j]);
                wmma::mma_sync(acc[i][j], ah[i],  blo, acc[i][j]);
                wmma::mma_sync(acc[i][j], alo[i], bh,  acc[i][j]);
            }
        }
    }
    __syncthreads();   // all warps done reading xh/xl before overwrite as C

    #pragma unroll
    for (int i = 0; i < 2; i++)
        #pragma unroll
        for (int j = 0; j < 2; j++)
            wmma::store_matrix_sync(Cs + (wr * 32 + i * 16) * LDC + wc * 32 + j * 16,
                                    acc[i][j], LDC, wmma::mem_row_major);
    __syncthreads();

    // epilogue: warp owns 8 rows (all 128 cols across 32 lanes x 4 cols)
    int lane = t & 31;
    int cj = lane * 4;
    int r0 = w * 8;
    float4 a4 = make_float4(0.f, 0.f, 0.f, 0.f), r4 = a4;
    if (al != nullptr) {
        a4 = ((const float4*)al)[lane];
        r4 = ((const float4*)ar)[lane];
    }
    #pragma unroll
    for (int r = 0; r < 8; r++) {
        int row = row0 + r0 + r;
        float4 v;
        v.x = Cs[(r0 + r) * LDC + cj + 0];
        v.y = Cs[(r0 + r) * LDC + cj + 1];
        v.z = Cs[(r0 + r) * LDC + cj + 2];
        v.w = Cs[(r0 + r) * LDC + cj + 3];
        if (row < nrows) {
            if (Yh) {
                __half2 p0 = __floats2half2_rn(v.x, v.y);
                __half2 p1 = __floats2half2_rn(v.z, v.w);
                unsigned u0 = *(unsigned*)&p0;
                unsigned u1 = *(unsigned*)&p1;
                ((uint2*)Yh)[(size_t)row * 32 + lane] = make_uint2(u0, u1);
            }
            if (Yf)
                *(float4*)(Yf + (size_t)row * 128 + cj) = v;
        }
        if (al != nullptr) {
            float pl = v.x * a4.x + v.y * a4.y + v.z * a4.z + v.w * a4.w;
            float pr = v.x * r4.x + v.y * r4.y + v.z * r4.z + v.w * r4.w;
            #pragma unroll
            for (int o = 16; o; o >>= 1) {
                pl += __shfl_xor_sync(0xffffffffu, pl, o);
                pr += __shfl_xor_sync(0xffffffffu, pr, o);
            }
            if (lane == 0 && row < nrows) { g_el[row] = pl; g_er[row] = pr; }
        }
    }
}

// ---------------- fused softmax-attention + aggregation, one warp per dst node ----------------
// 2-pass max-free softmax. pass A: p=exp(leaky(el+er)) packed WITH src id into
// g_epk (one 8B store). pass B: ONE 8B broadcast load per edge + fp16 row gather.
__global__ void k_node(const float* __restrict__ bvec, int do_relu) {
    int gw = (blockIdx.x * blockDim.x + threadIdx.x) >> 5;
    int lane = threadIdx.x & 31;
    if (gw >= N_NODES) return;
    int start = g_rowptr[gw];
    int end   = g_rowptr[gw + 1];
    float eld = g_el[gw];

    // pass A: exp(score) + segment sum; pack (weight, src) into one float2
    float ssum = 0.f;
    for (int i = start + lane; i < end; i += 32) {
        int s = g_esrc[i];
        float e = eld + g_er[s];
        e = (e > 0.f) ? e : 0.2f * e;     // leaky_relu 0.2
        float p = __expf(e);
        g_epk[i] = make_float2(p, __int_as_float(s));
        ssum += p;
    }
    #pragma unroll
    for (int o = 16; o; o >>= 1) ssum += __shfl_xor_sync(0xffffffffu, ssum, o);
    float inv = 1.f / (ssum + 1e-10f);
    __syncwarp();   // make cross-lane g_epk writes visible

    // pass B: single broadcast float2 load per edge + weighted fp16 gather
    float4 acc = make_float4(0.f, 0.f, 0.f, 0.f);
    const uint2* H2 = (const uint2*)g_Hh;
    #pragma unroll 4
    for (int i = start; i < end; i++) {
        float2 pk = g_epk[i];             // one 8B broadcast load
        float a = pk.x * inv;
        int s = __float_as_int(pk.y);
        uint2 raw = H2[(size_t)s * 32 + lane];
        __half2 h0 = *(__half2*)&raw.x;
        __half2 h1 = *(__half2*)&raw.y;
        float2 f0 = __half22float2(h0);
        float2 f1 = __half22float2(h1);
        acc.x += a * f0.x; acc.y += a * f0.y;
        acc.z += a * f1.x; acc.w += a * f1.y;
    }

    float4 b4 = ((const float4*)bvec)[lane];
    float4 o4 = make_float4(acc.x + b4.x, acc.y + b4.y, acc.z + b4.z, acc.w + b4.w);
    if (do_relu) {
        o4.x = fmaxf(o4.x, 0.f); o4.y = fmaxf(o4.y, 0.f);
        o4.z = fmaxf(o4.z, 0.f); o4.w = fmaxf(o4.w, 0.f);
    }
    ((float4*)g_X)[(size_t)gw * 32 + lane] = o4;
}

// ---------------- bilinear head: scores[m][s] = dot(T[m], server[s]) + bb ----------------
__global__ void k_scores(const float* __restrict__ bb, float* __restrict__ out) {
    __shared__ __align__(16) float Tm[16][132];
    __shared__ __align__(16) float Ss[16][132];
    int tx = threadIdx.x;       // s within tile
    int ty = threadIdx.y;       // m within tile
    int m0 = blockIdx.x * 16, s0 = blockIdx.y * 16;
    int t = ty * 16 + tx;
    for (int i = t; i < 512; i += 256) {
        int r = i >> 5, c = i & 31;
        float4 v = ((const float4*)g_T)[(size_t)(m0 + r) * 32 + c];
        *(float4*)&Tm[r][c * 4] = v;
        float4 w = ((const float4*)g_X)[(size_t)(NUC + NMC + s0 + r) * 32 + c];
        *(float4*)&Ss[r][c * 4] = w;
    }
    __syncthreads();
    float4 acc = make_float4(0.f, 0.f, 0.f, 0.f);
    #pragma unroll 8
    for (int k = 0; k < 32; k++) {
        float4 a = *(const float4*)&Tm[ty][k * 4];
        float4 b = *(const float4*)&Ss[tx][k * 4];
        acc.x += a.x * b.x; acc.y += a.y * b.y;
        acc.z += a.z * b.z; acc.w += a.w * b.w;
    }
    out[(m0 + ty) * NSC + (s0 + tx)] = acc.x + acc.y + acc.z + acc.w + bb[0];
}

// ---------------- host ----------------
extern "C" void kernel_launch(void* const* d_in, const int* in_sizes, int n_in,
                              void* d_out, int out_size) {
    const float* x   = (const float*)d_in[0];
    const int*   ei  = (const int*)  d_in[1];
    const int*   src = ei;
    const int*   dst = ei + NEDGE;
    const float* W1  = (const float*)d_in[2];
    const float* al1 = (const float*)d_in[3];
    const float* ar1 = (const float*)d_in[4];
    const float* b1  = (const float*)d_in[5];
    const float* W2  = (const float*)d_in[6];
    const float* al2 = (const float*)d_in[7];
    const float* ar2 = (const float*)d_in[8];
    const float* b2  = (const float*)d_in[9];
    const float* W3  = (const float*)d_in[10];
    const float* al3 = (const float*)d_in[11];
    const float* ar3 = (const float*)d_in[12];
    const float* b3  = (const float*)d_in[13];
    const float* Wb  = (const float*)d_in[14];
    const float* bb  = (const float*)d_in[15];
    float* out = (float*)d_out;

    void *pX_, *pHh_, *pT_, *pWh_, *pWl_;
    cudaGetSymbolAddress(&pX_, g_X);
    cudaGetSymbolAddress(&pHh_, g_Hh);
    cudaGetSymbolAddress(&pT_, g_T);
    cudaGetSymbolAddress(&pWh_, g_Wh);
    cudaGetSymbolAddress(&pWl_, g_Wl);
    float*  pX = (float*)pX_;
    __half* pH = (__half*)pHh_;
    float*  pT = (float*)pT_;
    __half* pWh = (__half*)pWh_;
    __half* pWl = (__half*)pWl_;

    const int smem_bytes = 4 * 128 * LDH * 2;   // xh+xl+whs+wls = 139264 B
    cudaFuncSetAttribute(k_gemm, cudaFuncAttributeMaxDynamicSharedMemorySize, smem_bytes);

    int warpgrid = (N_NODES * 32 + 255) / 256;
    int gemmgrid = (N_NODES + 127) / 128;

    // Fork a side stream for the CSR build so it overlaps the (independent)
    // weight split + layer-1 GEMM on the main (captured) stream.
    cudaStream_t s2;
    cudaStreamCreate(&s2);
    cudaEvent_t evFork, evCsr;
    cudaEventCreateWithFlags(&evFork, cudaEventDisableTiming);
    cudaEventCreateWithFlags(&evCsr, cudaEventDisableTiming);

    cudaEventRecord(evFork, 0);
    cudaStreamWaitEvent(s2, evFork, 0);

    // side stream: CSR build (dst-sorted edge list)
    k_count  <<<(NEDGE / 4 + 255) / 256, 256, 0, s2>>>(dst);
    k_scan1  <<<NB, 256, 0, s2>>>();
    k_scan2  <<<1, 256, 0, s2>>>();
    k_scan3  <<<NB, 256, 0, s2>>>();
    k_scatter<<<(NEDGE / 4 + 255) / 256, 256, 0, s2>>>(src, dst);
    cudaEventRecord(evCsr, s2);

    // main stream: weight split + layer-1 GEMM (no CSR dependency)
    k_splitw <<<64, 256>>>(W1, W2, W3, Wb);
    k_gemm<<<gemmgrid, 512, smem_bytes>>>(x, pWh, pWl, nullptr, pH, N_NODES, al1, ar1);

    // join: layer-1 aggregation needs both CSR and GEMM-1
    cudaStreamWaitEvent(0, evCsr, 0);
    k_node<<<warpgrid, 256>>>(b1, 1);
    // layer 2
    k_gemm<<<gemmgrid, 512, smem_bytes>>>(pX, pWh + 1 * HDIM * HDIM, pWl + 1 * HDIM * HDIM,
                                          nullptr, pH, N_NODES, al2, ar2);
    k_node<<<warpgrid, 256>>>(b2, 1);
    // layer 3 (no relu)
    k_gemm<<<gemmgrid, 512, smem_bytes>>>(pX, pWh + 2 * HDIM * HDIM, pWl + 2 * HDIM * HDIM,
                                          nullptr, pH, N_NODES, al3, ar3);
    k_node<<<warpgrid, 256>>>(b3, 0);

    // bilinear head
    k_gemm<<<(NMC + 127) / 128, 512, smem_bytes>>>(pX + (size_t)NUC * HDIM,
                                                   pWh + 3 * HDIM * HDIM, pWl + 3 * HDIM * HDIM,
                                                   pT, nullptr, NMC, nullptr, nullptr);
    k_scores<<<dim3(NMC / 16, NSC / 16), dim3(16, 16)>>>(bb, out);

    cudaEventDestroy(evFork);
    cudaEventDestroy(evCsr);
    cudaStreamDestroy(s2);
}